// round 8
// baseline (speedup 1.0000x reference)
#include <cuda_runtime.h>
#include <cuda_fp16.h>
#include <math.h>
#include <stdint.h>

#define BB 4
#define SS 2048
#define DD 1024

// ---------------- device scratch ----------------
__device__ __half g_xh[BB * SS * DD];
__device__ __half g_Wqh[DD * DD];
__device__ __half g_Wkh[DD * DD];
__device__ __half g_Wvh[DD * DD];
__device__ __half g_Qh[BB * SS * DD];
__device__ __half g_Kh[BB * SS * DD];
__device__ __half g_Vth[BB * SS * DD];        // [B][D][S]
__device__ float  g_Sc[(size_t)BB * SS * SS]; // fp32 logits
__device__ __half g_Ph[(size_t)BB * SS * SS]; // probs

// ---------------- helpers ----------------
__device__ __forceinline__ uint32_t smem_u32(const void* p) {
    uint32_t a;
    asm("{ .reg .u64 t; cvta.to.shared.u64 t, %1; cvt.u32.u64 %0, t; }" : "=r"(a) : "l"(p));
    return a;
}
__device__ __forceinline__ void cp16(uint32_t s, const void* g) {
    asm volatile("cp.async.cg.shared.global [%0], [%1], 16;" :: "r"(s), "l"(g) : "memory");
}
#define CP_COMMIT() asm volatile("cp.async.commit_group;" ::: "memory")
#define CP_WAIT(n)  asm volatile("cp.async.wait_group %0;" :: "n"(n) : "memory")

__device__ __forceinline__ void ldm4(uint32_t* r, uint32_t a) {
    asm volatile("ldmatrix.sync.aligned.m8n8.x4.shared.b16 {%0,%1,%2,%3}, [%4];"
                 : "=r"(r[0]), "=r"(r[1]), "=r"(r[2]), "=r"(r[3]) : "r"(a));
}
__device__ __forceinline__ void mma16816(float* d, const uint32_t* a, uint32_t b0, uint32_t b1) {
    asm volatile(
        "mma.sync.aligned.m16n8k16.row.col.f32.f16.f16.f32 "
        "{%0,%1,%2,%3}, {%4,%5,%6,%7}, {%8,%9}, {%0,%1,%2,%3};"
        : "+f"(d[0]), "+f"(d[1]), "+f"(d[2]), "+f"(d[3])
        : "r"(a[0]), "r"(a[1]), "r"(a[2]), "r"(a[3]), "r"(b0), "r"(b1));
}

// ---------------------------------------------------------------------------
// Plain-fp16 NT GEMM: C[M,N] = A[M,K] @ B[N,K]^T  (+bias / *alpha)
// CTA 128x128, 4 warps (warp tile 64x64), k-tile 32.
// All 16 LDSM for a k-tile issued up front, then 64 HMMA (4 HMMA/LDSM).
// 4-stage cp.async pipeline, ONE __syncthreads per k-iter, 2 CTAs/SM.
// EPI 0: +bias, fp16 store (Q, K)
// EPI 1: +bias, transpose, fp16 store (Vt[d][s])
// EPI 2: *alpha, fp32 store (scores / out)
// ---------------------------------------------------------------------------
static constexpr int STG    = 20480;             // 2 tiles x 10240 B
static constexpr int STAGES = 4;
static constexpr int SMEMB  = STAGES * STG;      // 81920 -> 2 CTAs/SM

template <int EPI>
__global__ __launch_bounds__(128, 2)
void hgemm(const __half* __restrict__ Ah, const __half* __restrict__ Bh,
           const float* __restrict__ bias,
           float* __restrict__ Cf, __half* __restrict__ Ch,
           int lda, int ldb, int ldc, int K, float alpha,
           long long sA, long long sB, long long sC)
{
    extern __shared__ char smem[];
    const uint32_t sbase = smem_u32(smem);
    const int t    = threadIdx.x;
    const int lane = t & 31;
    const int wid  = t >> 5;         // 0..3
    const int wm   = wid >> 1;       // 0..1
    const int wn   = wid & 1;        // 0..1
    const int lr   = lane & 15;
    const int lh   = lane >> 4;

    const long long bz = blockIdx.z;
    Ah += bz * sA;
    Bh += bz * sB;

    const int row0 = blockIdx.y * 128;
    const int col0 = blockIdx.x * 128;

    float acc[4][8][4];
#pragma unroll
    for (int i = 0; i < 4; i++)
#pragma unroll
        for (int j = 0; j < 8; j++)
#pragma unroll
            for (int r = 0; r < 4; r++) acc[i][j][r] = 0.0f;

    auto load_tile = [&](int jt, int s) {
        const uint32_t dstb = sbase + s * STG;
#pragma unroll
        for (int q = 0; q < 8; q++) {
            int idx = q * 128 + t;          // 0..1023
            int arr = idx >> 9;             // 0:A 1:B
            int rem = idx & 511;
            int row = rem >> 2;
            int ch  = rem & 3;
            const __half* src = (arr == 0) ? (Ah + (size_t)(row0 + row) * lda)
                                           : (Bh + (size_t)(col0 + row) * ldb);
            src += jt * 32 + ch * 8;
            cp16(dstb + arr * 10240u + row * 80u + ch * 16u, src);
        }
    };

    auto compute = [&](uint32_t sb) {
        uint32_t ah[2][4][4], bhf[2][4][4];
#pragma unroll
        for (int kb = 0; kb < 2; kb++) {
            const int kk = kb * 16;
#pragma unroll
            for (int i = 0; i < 4; i++) {
                uint32_t ra = (uint32_t)(((wm * 64 + i * 16 + lr) * 40 + kk + 8 * lh) * 2);
                ldm4(ah[kb][i], sb + ra);
            }
#pragma unroll
            for (int j2 = 0; j2 < 4; j2++) {
                uint32_t rb = (uint32_t)(((wn * 64 + j2 * 16 + lr) * 40 + kk + 8 * lh) * 2);
                ldm4(bhf[kb][j2], sb + 10240u + rb);
            }
        }
#pragma unroll
        for (int kb = 0; kb < 2; kb++)
#pragma unroll
            for (int i = 0; i < 4; i++)
#pragma unroll
                for (int j = 0; j < 8; j++) {
                    const int j2 = j >> 1, sl = j & 1;
                    mma16816(acc[i][j], ah[kb][i], bhf[kb][j2][sl], bhf[kb][j2][sl + 2]);
                }
    };

    const int KT = K >> 5;
    load_tile(0, 0); CP_COMMIT();
    load_tile(1, 1); CP_COMMIT();

    for (int kt = 0; kt < KT; kt++) {
        const int j = kt + 2;
        if (j < KT) load_tile(j, j & 3);
        CP_COMMIT();
        CP_WAIT(2);
        __syncthreads();
        compute(sbase + (uint32_t)((kt & 3) * STG));
    }

    // ---------------- epilogue ----------------
    const int g  = lane >> 2;
    const int tq = lane & 3;

    if (EPI == 2) {
#pragma unroll
        for (int i = 0; i < 4; i++) {
            int r0 = row0 + wm * 64 + i * 16 + g;
#pragma unroll
            for (int j = 0; j < 8; j++) {
                int c = col0 + wn * 64 + j * 8 + tq * 2;
                float2 v0 = make_float2(acc[i][j][0] * alpha, acc[i][j][1] * alpha);
                float2 v1 = make_float2(acc[i][j][2] * alpha, acc[i][j][3] * alpha);
                *(float2*)(Cf + bz * sC + (size_t)r0 * ldc + c)       = v0;
                *(float2*)(Cf + bz * sC + (size_t)(r0 + 8) * ldc + c) = v1;
            }
        }
    } else if (EPI == 0) {
#pragma unroll
        for (int i = 0; i < 4; i++) {
            int r0 = row0 + wm * 64 + i * 16 + g;
#pragma unroll
            for (int j = 0; j < 8; j++) {
                int c = col0 + wn * 64 + j * 8 + tq * 2;
                float bx = bias[c], by = bias[c + 1];
#pragma unroll
                for (int h = 0; h < 2; h++) {
                    float vx = acc[i][j][2 * h + 0] + bx;
                    float vy = acc[i][j][2 * h + 1] + by;
                    size_t off = (size_t)(r0 + 8 * h) * ldc + c;
                    *(__half2*)(Ch + off) =
                        __halves2half2(__float2half_rn(vx), __float2half_rn(vy));
                }
            }
        }
    } else {  // EPI == 1 : transpose to Vt[d][s]
        __syncthreads();
        __half* hs = (__half*)smem;             // [128 c][136 m] halves = 34816B
#pragma unroll
        for (int i = 0; i < 4; i++) {
            int m0 = wm * 64 + i * 16 + g;
#pragma unroll
            for (int j = 0; j < 8; j++) {
                int c = wn * 64 + j * 8 + tq * 2;
                float bx = bias[col0 + c], by = bias[col0 + c + 1];
#pragma unroll
                for (int h = 0; h < 2; h++) {
                    int m = m0 + 8 * h;
                    hs[(c + 0) * 136 + m] = __float2half_rn(acc[i][j][2 * h + 0] + bx);
                    hs[(c + 1) * 136 + m] = __float2half_rn(acc[i][j][2 * h + 1] + by);
                }
            }
        }
        __syncthreads();
        const int b  = row0 >> 11;
        const int s0 = row0 & 2047;
        const int cb = t >> 4;            // 0..7
        const int m  = (t & 15) * 8;      // 0..120
        __half* Vh = Ch + (size_t)b * DD * SS;
#pragma unroll 4
        for (int cc = cb; cc < 128; cc += 8) {
            size_t off = (size_t)(col0 + cc) * SS + s0 + m;
            *(__half2*)(Vh + off)     = *(__half2*)(hs + cc * 136 + m);
            *(__half2*)(Vh + off + 2) = *(__half2*)(hs + cc * 136 + m + 2);
            *(__half2*)(Vh + off + 4) = *(__half2*)(hs + cc * 136 + m + 4);
            *(__half2*)(Vh + off + 6) = *(__half2*)(hs + cc * 136 + m + 6);
        }
    }
}

// ---------------------------------------------------------------------------
// fp32 -> fp16 convert, vectorized
// ---------------------------------------------------------------------------
__global__ __launch_bounds__(256)
void cvt_kernel(const float* __restrict__ in, __half* __restrict__ hi, int n4)
{
    int i = blockIdx.x * 256 + threadIdx.x;
    if (i >= n4) return;
    float4 v = ((const float4*)in)[i];
    ((__half2*)hi)[2 * i + 0] = __halves2half2(__float2half_rn(v.x), __float2half_rn(v.y));
    ((__half2*)hi)[2 * i + 1] = __halves2half2(__float2half_rn(v.z), __float2half_rn(v.w));
}

// fused convert of the 3 weight matrices
__global__ __launch_bounds__(256)
void cvt3_kernel(const float* __restrict__ w0, const float* __restrict__ w1,
                 const float* __restrict__ w2,
                 __half* __restrict__ h0, __half* __restrict__ h1,
                 __half* __restrict__ h2, int n4)
{
    int i = blockIdx.x * 256 + threadIdx.x;
    if (i >= n4) return;
    const float* in = (blockIdx.y == 0) ? w0 : (blockIdx.y == 1) ? w1 : w2;
    __half* hi = (blockIdx.y == 0) ? h0 : (blockIdx.y == 1) ? h1 : h2;
    float4 v = ((const float4*)in)[i];
    ((__half2*)hi)[2 * i + 0] = __halves2half2(__float2half_rn(v.x), __float2half_rn(v.y));
    ((__half2*)hi)[2 * i + 1] = __halves2half2(__float2half_rn(v.z), __float2half_rn(v.w));
}

// ---------------------------------------------------------------------------
// Masked softmax over rows of Sc [B*S, S]; writes fp16 probs.
// ---------------------------------------------------------------------------
__global__ __launch_bounds__(256)
void softmax_mask_kernel(const float* __restrict__ Sc, const int* __restrict__ mask,
                         __half* __restrict__ Ph)
{
    const int r = blockIdx.x;
    const int b = r >> 11;
    const float4* row = (const float4*)(Sc + (size_t)r * SS);
    const int4* mrow = (const int4*)(mask + (size_t)b * SS);
    const int t = threadIdx.x;
    const int w = t >> 5;

    float4 v0 = row[t], v1 = row[t + 256];
    int4   m0 = mrow[t], m1 = mrow[t + 256];

    const float NI = -INFINITY;
    float mx = NI;
    mx = fmaxf(mx, m0.x ? v0.x : NI); mx = fmaxf(mx, m0.y ? v0.y : NI);
    mx = fmaxf(mx, m0.z ? v0.z : NI); mx = fmaxf(mx, m0.w ? v0.w : NI);
    mx = fmaxf(mx, m1.x ? v1.x : NI); mx = fmaxf(mx, m1.y ? v1.y : NI);
    mx = fmaxf(mx, m1.z ? v1.z : NI); mx = fmaxf(mx, m1.w ? v1.w : NI);
#pragma unroll
    for (int o = 16; o; o >>= 1) mx = fmaxf(mx, __shfl_xor_sync(0xffffffffu, mx, o));
    __shared__ float red[8];
    if ((t & 31) == 0) red[w] = mx;
    __syncthreads();
    mx = fmaxf(fmaxf(fmaxf(red[0], red[1]), fmaxf(red[2], red[3])),
               fmaxf(fmaxf(red[4], red[5]), fmaxf(red[6], red[7])));

    float e[8];
    e[0] = m0.x ? __expf(v0.x - mx) : 0.f; e[1] = m0.y ? __expf(v0.y - mx) : 0.f;
    e[2] = m0.z ? __expf(v0.z - mx) : 0.f; e[3] = m0.w ? __expf(v0.w - mx) : 0.f;
    e[4] = m1.x ? __expf(v1.x - mx) : 0.f; e[5] = m1.y ? __expf(v1.y - mx) : 0.f;
    e[6] = m1.z ? __expf(v1.z - mx) : 0.f; e[7] = m1.w ? __expf(v1.w - mx) : 0.f;
    float sum = ((e[0] + e[1]) + (e[2] + e[3])) + ((e[4] + e[5]) + (e[6] + e[7]));
#pragma unroll
    for (int o = 16; o; o >>= 1) sum += __shfl_xor_sync(0xffffffffu, sum, o);
    __syncthreads();
    if ((t & 31) == 0) red[w] = sum;
    __syncthreads();
    sum = ((red[0] + red[1]) + (red[2] + red[3])) + ((red[4] + red[5]) + (red[6] + red[7]));
    const float inv = 1.0f / sum;

    __half2* ph = (__half2*)(Ph + (size_t)r * SS);
#pragma unroll
    for (int h = 0; h < 2; h++) {
        float p0 = e[4 * h + 0] * inv, p1 = e[4 * h + 1] * inv;
        float p2 = e[4 * h + 2] * inv, p3 = e[4 * h + 3] * inv;
        int base = h * 512 + 2 * t;
        ph[base + 0] = __halves2half2(__float2half_rn(p0), __float2half_rn(p1));
        ph[base + 1] = __halves2half2(__float2half_rn(p2), __float2half_rn(p3));
    }
}

// ---------------------------------------------------------------------------
extern "C" void kernel_launch(void* const* d_in, const int* in_sizes, int n_in,
                              void* d_out, int out_size)
{
    const float* x    = (const float*)d_in[0];
    const int*   mask = (const int*)  d_in[1];
    const float* Wq   = (const float*)d_in[2];
    const float* bq   = (const float*)d_in[3];
    const float* Wk   = (const float*)d_in[4];
    const float* bk   = (const float*)d_in[5];
    const float* Wv   = (const float*)d_in[6];
    const float* bv   = (const float*)d_in[7];
    float* out = (float*)d_out;

    __half *xh, *Wqh, *Wkh, *Wvh, *Qh, *Kh, *Vth, *Ph;
    float* Sc;
    cudaGetSymbolAddress((void**)&xh,  g_xh);
    cudaGetSymbolAddress((void**)&Wqh, g_Wqh);
    cudaGetSymbolAddress((void**)&Wkh, g_Wkh);
    cudaGetSymbolAddress((void**)&Wvh, g_Wvh);
    cudaGetSymbolAddress((void**)&Qh,  g_Qh);
    cudaGetSymbolAddress((void**)&Kh,  g_Kh);
    cudaGetSymbolAddress((void**)&Vth, g_Vth);
    cudaGetSymbolAddress((void**)&Ph,  g_Ph);
    cudaGetSymbolAddress((void**)&Sc,  g_Sc);

    cudaFuncSetAttribute(hgemm<0>, cudaFuncAttributeMaxDynamicSharedMemorySize, SMEMB);
    cudaFuncSetAttribute(hgemm<1>, cudaFuncAttributeMaxDynamicSharedMemorySize, SMEMB);
    cudaFuncSetAttribute(hgemm<2>, cudaFuncAttributeMaxDynamicSharedMemorySize, SMEMB);

    // launches #0,#1: converts
    cvt_kernel<<<BB * SS * DD / 4 / 256, 256>>>(x, xh, BB * SS * DD / 4);
    {
        dim3 g(DD * DD / 4 / 256, 3);
        cvt3_kernel<<<g, 256>>>(Wq, Wk, Wv, Wqh, Wkh, Wvh, DD * DD / 4);
    }

    const int M = BB * SS;  // 8192

    // launches #2,#3,#4: QKV projections (NT): [M,D] = xh @ Wh^T + b
    {
        dim3 g(DD / 128, M / 128, 1);
        hgemm<0><<<g, 128, SMEMB>>>(xh, Wqh, bq, nullptr, Qh,
                                    DD, DD, DD, DD, 1.0f, 0, 0, 0);
        hgemm<0><<<g, 128, SMEMB>>>(xh, Wkh, bk, nullptr, Kh,
                                    DD, DD, DD, DD, 1.0f, 0, 0, 0);
        hgemm<1><<<g, 128, SMEMB>>>(xh, Wvh, bv, nullptr, Vth,
                                    DD, DD, 0, DD, 1.0f, 0, 0, 0);
    }

    // launch #5 (ncu capture target): scores[b] = (1/32) * Qh[b] @ Kh[b]^T
    {
        dim3 g(SS / 128, SS / 128, BB);
        hgemm<2><<<g, 128, SMEMB>>>(Qh, Kh, nullptr, Sc, nullptr,
                                    DD, DD, SS, DD, 1.0f / 32.0f,
                                    (long long)SS * DD, (long long)SS * DD,
                                    (long long)SS * SS);
    }

    // masked softmax -> fp16 probs
    softmax_mask_kernel<<<BB * SS, 256>>>(Sc, mask, Ph);

    // out[b] = Ph[b] @ Vth[b]^T
    {
        dim3 g(DD / 128, SS / 128, BB);
        hgemm<2><<<g, 128, SMEMB>>>(Ph, Vth, nullptr, out, nullptr,
                                    SS, SS, DD, SS, 1.0f,
                                    (long long)SS * SS, (long long)DD * SS,
                                    (long long)SS * DD);
    }
}

// round 9
// speedup vs baseline: 1.5975x; 1.5975x over previous
#include <cuda_runtime.h>
#include <cuda_fp16.h>
#include <math.h>
#include <stdint.h>

#define BB 4
#define SS 2048
#define DD 1024

// ---------------- device scratch ----------------
__device__ __half g_xh[BB * SS * DD];
__device__ __half g_xc[BB * SS * DD];         // compacted (kept) rows of xh
__device__ __half g_Wqh[DD * DD];
__device__ __half g_Wkh[DD * DD];
__device__ __half g_Wvh[DD * DD];
__device__ __half g_Qh[BB * SS * DD];
__device__ __half g_Kc[BB * SS * DD];         // compacted K
__device__ __half g_Vtc[BB * SS * DD];        // compacted V, [B][D][j]
__device__ float  g_Sc[(size_t)BB * SS * SS]; // fp32 logits (compacted cols)
__device__ __half g_Ph[(size_t)BB * SS * SS]; // probs (compacted cols)
__device__ int    g_idx[BB * SS];
__device__ int    g_nkeep[BB];
__device__ int    g_npad[BB];

// ---------------- helpers ----------------
__device__ __forceinline__ uint32_t smem_u32(const void* p) {
    uint32_t a;
    asm("{ .reg .u64 t; cvta.to.shared.u64 t, %1; cvt.u32.u64 %0, t; }" : "=r"(a) : "l"(p));
    return a;
}
__device__ __forceinline__ void cp16(uint32_t s, const void* g) {
    asm volatile("cp.async.cg.shared.global [%0], [%1], 16;" :: "r"(s), "l"(g) : "memory");
}
#define CP_COMMIT() asm volatile("cp.async.commit_group;" ::: "memory")
#define CP_WAIT(n)  asm volatile("cp.async.wait_group %0;" :: "n"(n) : "memory")

__device__ __forceinline__ void ldm4(uint32_t* r, uint32_t a) {
    asm volatile("ldmatrix.sync.aligned.m8n8.x4.shared.b16 {%0,%1,%2,%3}, [%4];"
                 : "=r"(r[0]), "=r"(r[1]), "=r"(r[2]), "=r"(r[3]) : "r"(a));
}
__device__ __forceinline__ void mma16816(float* d, const uint32_t* a, uint32_t b0, uint32_t b1) {
    asm volatile(
        "mma.sync.aligned.m16n8k16.row.col.f32.f16.f16.f32 "
        "{%0,%1,%2,%3}, {%4,%5,%6,%7}, {%8,%9}, {%0,%1,%2,%3};"
        : "+f"(d[0]), "+f"(d[1]), "+f"(d[2]), "+f"(d[3])
        : "r"(a[0]), "r"(a[1]), "r"(a[2]), "r"(a[3]), "r"(b0), "r"(b1));
}

// ---------------------------------------------------------------------------
// Plain-fp16 NT GEMM (round-7 config): CTA 128x128, 8 warps (64x32 warp tile),
// k-tile 32, 4-stage cp.async pipeline, one __syncthreads per k-iter, 2 CTA/SM.
// New: per-batch dynamic limits (device-side, graph-safe):
//   mLim: skip CTA if row0 >= mLim[bz]    (compacted-M projections)
//   nLim: skip CTA if col0 >= nLim[bz]    (compacted-N scores)
//   kd:   K-dim = kd[bz]                  (compacted-K attn.V)
// C pointers are offset by bz*sC uniformly.
// EPI 0: +bias fp16 store   EPI 1: +bias transpose fp16 store (Vt[d][j])
// EPI 2: *alpha fp32 store
// ---------------------------------------------------------------------------
static constexpr int STG    = 20480;
static constexpr int STAGES = 4;
static constexpr int SMEMB  = STAGES * STG;      // 81920

template <int EPI>
__global__ __launch_bounds__(256, 2)
void hgemm(const __half* __restrict__ Ah, const __half* __restrict__ Bh,
           const float* __restrict__ bias,
           float* __restrict__ Cf, __half* __restrict__ Ch,
           int lda, int ldb, int ldc, int K, float alpha,
           long long sA, long long sB, long long sC,
           const int* __restrict__ mLim, const int* __restrict__ nLim,
           const int* __restrict__ kd)
{
    extern __shared__ char smem[];
    const uint32_t sbase = smem_u32(smem);
    const int t    = threadIdx.x;
    const int lane = t & 31;
    const int wid  = t >> 5;
    const int wm   = wid >> 2;
    const int wn   = wid & 3;
    const int lr   = lane & 15;
    const int lh   = lane >> 4;

    const long long bz = blockIdx.z;
    const int row0 = blockIdx.y * 128;
    const int col0 = blockIdx.x * 128;
    if (mLim && row0 >= mLim[bz]) return;
    if (nLim && col0 >= nLim[bz]) return;
    if (kd) K = kd[bz];

    Ah += bz * sA;
    Bh += bz * sB;
    if (Cf) Cf += bz * sC;
    if (Ch) Ch += bz * sC;

    float acc[4][4][4];
#pragma unroll
    for (int i = 0; i < 4; i++)
#pragma unroll
        for (int j = 0; j < 4; j++)
#pragma unroll
            for (int r = 0; r < 4; r++) acc[i][j][r] = 0.0f;

    auto load_tile = [&](int jt, int s) {
        const uint32_t dstb = sbase + s * STG;
#pragma unroll
        for (int q = 0; q < 4; q++) {
            int idx = q * 256 + t;
            int arr = idx >> 9;
            int rem = idx & 511;
            int row = rem >> 2;
            int ch  = rem & 3;
            const __half* src = (arr == 0) ? (Ah + (size_t)(row0 + row) * lda)
                                           : (Bh + (size_t)(col0 + row) * ldb);
            src += jt * 32 + ch * 8;
            cp16(dstb + arr * 10240u + row * 80u + ch * 16u, src);
        }
    };

    auto compute = [&](uint32_t sb) {
#pragma unroll
        for (int kk = 0; kk < 32; kk += 16) {
            uint32_t ah[4][4], bh[2][4];
#pragma unroll
            for (int i = 0; i < 4; i++) {
                uint32_t ra = (uint32_t)(((wm * 64 + i * 16 + lr) * 40 + kk + 8 * lh) * 2);
                ldm4(ah[i], sb + ra);
            }
#pragma unroll
            for (int j2 = 0; j2 < 2; j2++) {
                uint32_t rb = (uint32_t)(((wn * 32 + j2 * 16 + lr) * 40 + kk + 8 * lh) * 2);
                ldm4(bh[j2], sb + 10240u + rb);
            }
#pragma unroll
            for (int i = 0; i < 4; i++)
#pragma unroll
                for (int j = 0; j < 4; j++) {
                    const int j2 = j >> 1, sl = j & 1;
                    mma16816(acc[i][j], ah[i], bh[j2][sl], bh[j2][sl + 2]);
                }
        }
    };

    const int KT = K >> 5;
    load_tile(0, 0); CP_COMMIT();
    load_tile(1, 1); CP_COMMIT();

    for (int kt = 0; kt < KT; kt++) {
        const int j = kt + 2;
        if (j < KT) load_tile(j, j & 3);
        CP_COMMIT();
        CP_WAIT(2);
        __syncthreads();
        compute(sbase + (uint32_t)((kt & 3) * STG));
    }

    // ---------------- epilogue ----------------
    const int g  = lane >> 2;
    const int tq = lane & 3;

    if (EPI == 2) {
#pragma unroll
        for (int i = 0; i < 4; i++) {
            int r0 = row0 + wm * 64 + i * 16 + g;
#pragma unroll
            for (int j = 0; j < 4; j++) {
                int c = col0 + wn * 32 + j * 8 + tq * 2;
                float2 v0 = make_float2(acc[i][j][0] * alpha, acc[i][j][1] * alpha);
                float2 v1 = make_float2(acc[i][j][2] * alpha, acc[i][j][3] * alpha);
                *(float2*)(Cf + (size_t)r0 * ldc + c)       = v0;
                *(float2*)(Cf + (size_t)(r0 + 8) * ldc + c) = v1;
            }
        }
    } else if (EPI == 0) {
#pragma unroll
        for (int i = 0; i < 4; i++) {
            int r0 = row0 + wm * 64 + i * 16 + g;
#pragma unroll
            for (int j = 0; j < 4; j++) {
                int c = col0 + wn * 32 + j * 8 + tq * 2;
                float bx = bias[c], by = bias[c + 1];
#pragma unroll
                for (int h = 0; h < 2; h++) {
                    float vx = acc[i][j][2 * h + 0] + bx;
                    float vy = acc[i][j][2 * h + 1] + by;
                    size_t off = (size_t)(r0 + 8 * h) * ldc + c;
                    *(__half2*)(Ch + off) =
                        __halves2half2(__float2half_rn(vx), __float2half_rn(vy));
                }
            }
        }
    } else {  // EPI == 1 : transpose, write Ch[(col0+c)*SS + row0 + m]
        __syncthreads();
        __half* hs = (__half*)smem;             // [128][136]
#pragma unroll
        for (int i = 0; i < 4; i++) {
            int m0 = wm * 64 + i * 16 + g;
#pragma unroll
            for (int j = 0; j < 4; j++) {
                int c = wn * 32 + j * 8 + tq * 2;
                float bx = bias[col0 + c], by = bias[col0 + c + 1];
#pragma unroll
                for (int h = 0; h < 2; h++) {
                    int m = m0 + 8 * h;
                    hs[(c + 0) * 136 + m] = __float2half_rn(acc[i][j][2 * h + 0] + bx);
                    hs[(c + 1) * 136 + m] = __float2half_rn(acc[i][j][2 * h + 1] + by);
                }
            }
        }
        __syncthreads();
        const int cb = t >> 5;
        const int m  = (t & 31) * 4;
#pragma unroll 4
        for (int cc = cb; cc < 128; cc += 8) {
            size_t off = (size_t)(col0 + cc) * SS + row0 + m;
            *(__half2*)(Ch + off)     = *(__half2*)(hs + cc * 136 + m);
            *(__half2*)(Ch + off + 2) = *(__half2*)(hs + cc * 136 + m + 2);
        }
    }
}

// ---------------------------------------------------------------------------
__global__ __launch_bounds__(256)
void cvt_kernel(const float* __restrict__ in, __half* __restrict__ hi, int n4)
{
    int i = blockIdx.x * 256 + threadIdx.x;
    if (i >= n4) return;
    float4 v = ((const float4*)in)[i];
    ((__half2*)hi)[2 * i + 0] = __halves2half2(__float2half_rn(v.x), __float2half_rn(v.y));
    ((__half2*)hi)[2 * i + 1] = __halves2half2(__float2half_rn(v.z), __float2half_rn(v.w));
}

__global__ __launch_bounds__(256)
void cvt3_kernel(const float* __restrict__ w0, const float* __restrict__ w1,
                 const float* __restrict__ w2,
                 __half* __restrict__ h0, __half* __restrict__ h1,
                 __half* __restrict__ h2, int n4)
{
    int i = blockIdx.x * 256 + threadIdx.x;
    if (i >= n4) return;
    const float* in = (blockIdx.y == 0) ? w0 : (blockIdx.y == 1) ? w1 : w2;
    __half* hi = (blockIdx.y == 0) ? h0 : (blockIdx.y == 1) ? h1 : h2;
    float4 v = ((const float4*)in)[i];
    ((__half2*)hi)[2 * i + 0] = __halves2half2(__float2half_rn(v.x), __float2half_rn(v.y));
    ((__half2*)hi)[2 * i + 1] = __halves2half2(__float2half_rn(v.z), __float2half_rn(v.w));
}

// ---------------------------------------------------------------------------
// Per-batch compaction of kept key indices (ascending). One block per batch.
// ---------------------------------------------------------------------------
__global__ __launch_bounds__(256)
void compact_kernel(const int* __restrict__ mask, int* __restrict__ idx,
                    int* __restrict__ nkeepA, int* __restrict__ npadA)
{
    const int b = blockIdx.x;
    const int t = threadIdx.x;
    const int* m = mask + (size_t)b * SS;
    __shared__ int cnt[257];
    int loc[8], c = 0;
#pragma unroll
    for (int i = 0; i < 8; i++) {
        loc[i] = (m[t * 8 + i] != 0);
        c += loc[i];
    }
    cnt[t + 1] = c;
    if (t == 0) cnt[0] = 0;
    __syncthreads();
    if (t == 0)
        for (int i = 1; i <= 256; i++) cnt[i] += cnt[i - 1];
    __syncthreads();
    int base = cnt[t];
#pragma unroll
    for (int i = 0; i < 8; i++)
        if (loc[i]) idx[(size_t)b * SS + (base++)] = t * 8 + i;
    if (t == 0) {
        int tot = cnt[256];
        nkeepA[b] = tot;
        npadA[b]  = (tot + 127) & ~127;
    }
}

// Gather compacted x rows (zero padding rows). grid (SS, B), 128 threads.
__global__ __launch_bounds__(128)
void gather_x(const __half* __restrict__ xh, const int* __restrict__ idx,
              const int* __restrict__ nkeepA, __half* __restrict__ xc)
{
    const int j = blockIdx.x, b = blockIdx.y, t = threadIdx.x;
    __half* dst = xc + ((size_t)b * SS + j) * DD;
    if (j < nkeepA[b]) {
        const __half* src = xh + ((size_t)b * SS + idx[(size_t)b * SS + j]) * DD;
        ((uint4*)dst)[t] = ((const uint4*)src)[t];
    } else {
        uint4 z = make_uint4(0, 0, 0, 0);
        ((uint4*)dst)[t] = z;
    }
}

// ---------------------------------------------------------------------------
// Softmax over compacted logits: row r, cols [0, npad[b]); cols >= nkeep -> 0.
// ---------------------------------------------------------------------------
__global__ __launch_bounds__(256)
void softmax2_kernel(const float* __restrict__ Sc, const int* __restrict__ nkeepA,
                     const int* __restrict__ npadA, __half* __restrict__ Ph)
{
    const int r = blockIdx.x;
    const int b = r >> 11;
    const int t = threadIdx.x;
    const int w = t >> 5;
    const int nk = nkeepA[b];
    const int np = npadA[b];
    const float4* row = (const float4*)(Sc + (size_t)r * SS);

    float4 v[2];
    int act[2];
    float mx = -INFINITY;
#pragma unroll
    for (int it = 0; it < 2; it++) {
        int i = it * 256 + t;          // float4 index, j = 4i
        act[it] = (i * 4 < np);
        if (act[it]) {
            v[it] = row[i];
            int j = i * 4;
            if (j + 0 < nk) mx = fmaxf(mx, v[it].x);
            if (j + 1 < nk) mx = fmaxf(mx, v[it].y);
            if (j + 2 < nk) mx = fmaxf(mx, v[it].z);
            if (j + 3 < nk) mx = fmaxf(mx, v[it].w);
        }
    }
#pragma unroll
    for (int o = 16; o; o >>= 1) mx = fmaxf(mx, __shfl_xor_sync(0xffffffffu, mx, o));
    __shared__ float red[8];
    if ((t & 31) == 0) red[w] = mx;
    __syncthreads();
    mx = fmaxf(fmaxf(fmaxf(red[0], red[1]), fmaxf(red[2], red[3])),
               fmaxf(fmaxf(red[4], red[5]), fmaxf(red[6], red[7])));

    float sum = 0.0f;
#pragma unroll
    for (int it = 0; it < 2; it++) {
        if (act[it]) {
            int i = it * 256 + t, j = i * 4;
            v[it].x = (j + 0 < nk) ? __expf(v[it].x - mx) : 0.f;
            v[it].y = (j + 1 < nk) ? __expf(v[it].y - mx) : 0.f;
            v[it].z = (j + 2 < nk) ? __expf(v[it].z - mx) : 0.f;
            v[it].w = (j + 3 < nk) ? __expf(v[it].w - mx) : 0.f;
            sum += (v[it].x + v[it].y) + (v[it].z + v[it].w);
        }
    }
#pragma unroll
    for (int o = 16; o; o >>= 1) sum += __shfl_xor_sync(0xffffffffu, sum, o);
    __syncthreads();
    if ((t & 31) == 0) red[w] = sum;
    __syncthreads();
    sum = ((red[0] + red[1]) + (red[2] + red[3])) + ((red[4] + red[5]) + (red[6] + red[7]));
    const float inv = 1.0f / sum;

    __half2* ph = (__half2*)(Ph + (size_t)r * SS);
#pragma unroll
    for (int it = 0; it < 2; it++) {
        if (act[it]) {
            int i = it * 256 + t;
            ph[2 * i + 0] = __halves2half2(__float2half_rn(v[it].x * inv),
                                           __float2half_rn(v[it].y * inv));
            ph[2 * i + 1] = __halves2half2(__float2half_rn(v[it].z * inv),
                                           __float2half_rn(v[it].w * inv));
        }
    }
}

// ---------------------------------------------------------------------------
extern "C" void kernel_launch(void* const* d_in, const int* in_sizes, int n_in,
                              void* d_out, int out_size)
{
    const float* x    = (const float*)d_in[0];
    const int*   mask = (const int*)  d_in[1];
    const float* Wq   = (const float*)d_in[2];
    const float* bq   = (const float*)d_in[3];
    const float* Wk   = (const float*)d_in[4];
    const float* bk   = (const float*)d_in[5];
    const float* Wv   = (const float*)d_in[6];
    const float* bv   = (const float*)d_in[7];
    float* out = (float*)d_out;

    __half *xh, *xc, *Wqh, *Wkh, *Wvh, *Qh, *Kc, *Vtc, *Ph;
    float* Sc;
    int *idx, *nkeep, *npad;
    cudaGetSymbolAddress((void**)&xh,   g_xh);
    cudaGetSymbolAddress((void**)&xc,   g_xc);
    cudaGetSymbolAddress((void**)&Wqh,  g_Wqh);
    cudaGetSymbolAddress((void**)&Wkh,  g_Wkh);
    cudaGetSymbolAddress((void**)&Wvh,  g_Wvh);
    cudaGetSymbolAddress((void**)&Qh,   g_Qh);
    cudaGetSymbolAddress((void**)&Kc,   g_Kc);
    cudaGetSymbolAddress((void**)&Vtc,  g_Vtc);
    cudaGetSymbolAddress((void**)&Ph,   g_Ph);
    cudaGetSymbolAddress((void**)&Sc,   g_Sc);
    cudaGetSymbolAddress((void**)&idx,  g_idx);
    cudaGetSymbolAddress((void**)&nkeep, g_nkeep);
    cudaGetSymbolAddress((void**)&npad, g_npad);

    cudaFuncSetAttribute(hgemm<0>, cudaFuncAttributeMaxDynamicSharedMemorySize, SMEMB);
    cudaFuncSetAttribute(hgemm<1>, cudaFuncAttributeMaxDynamicSharedMemorySize, SMEMB);
    cudaFuncSetAttribute(hgemm<2>, cudaFuncAttributeMaxDynamicSharedMemorySize, SMEMB);

    const long long sBD = (long long)SS * DD;

    // #0,#1: converts
    cvt_kernel<<<BB * SS * DD / 4 / 256, 256>>>(x, xh, BB * SS * DD / 4);
    {
        dim3 g(DD * DD / 4 / 256, 3);
        cvt3_kernel<<<g, 256>>>(Wq, Wk, Wv, Wqh, Wkh, Wvh, DD * DD / 4);
    }

    // #2: per-batch key compaction; #3: gather compacted x rows
    compact_kernel<<<BB, 256>>>(mask, idx, nkeep, npad);
    {
        dim3 g(SS, BB);
        gather_x<<<g, 128>>>(xh, idx, nkeep, xc);
    }

    // #4: Q projection, full M = B*S
    {
        dim3 g(DD / 128, BB * SS / 128, 1);
        hgemm<0><<<g, 256, SMEMB>>>(xh, Wqh, bq, nullptr, Qh,
                                    DD, DD, DD, DD, 1.0f, 0, 0, 0,
                                    nullptr, nullptr, nullptr);
    }
    // #5: K projection on compacted rows (early-exit beyond npad[b])
    {
        dim3 g(DD / 128, SS / 128, BB);
        hgemm<0><<<g, 256, SMEMB>>>(xc, Wkh, bk, nullptr, Kc,
                                    DD, DD, DD, DD, 1.0f, sBD, 0, sBD,
                                    npad, nullptr, nullptr);
    }
    // #6: V projection on compacted rows, transposed store -> Vtc[b][d][j]
    {
        dim3 g(DD / 128, SS / 128, BB);
        hgemm<1><<<g, 256, SMEMB>>>(xc, Wvh, bv, nullptr, Vtc,
                                    DD, DD, 0, DD, 1.0f, sBD, 0, sBD,
                                    npad, nullptr, nullptr);
    }
    // #7: scores[b] = (1/32) * Q[b] @ Kc[b]^T (compacted N, early-exit)
    {
        dim3 g(SS / 128, SS / 128, BB);
        hgemm<2><<<g, 256, SMEMB>>>(Qh, Kc, nullptr, Sc, nullptr,
                                    DD, DD, SS, DD, 1.0f / 32.0f,
                                    sBD, sBD, (long long)SS * SS,
                                    nullptr, npad, nullptr);
    }
    // #8: softmax over compacted cols
    softmax2_kernel<<<BB * SS, 256>>>(Sc, nkeep, npad, Ph);

    // #9: out[b] = Ph[b] @ Vtc[b]^T with dynamic K = npad[b]
    {
        dim3 g(DD / 128, SS / 128, BB);
        hgemm<2><<<g, 256, SMEMB>>>(Ph, Vtc, nullptr, out, nullptr,
                                    SS, SS, DD, DD, 1.0f,
                                    (long long)SS * SS, sBD, sBD,
                                    nullptr, nullptr, npad);
    }
}

// round 10
// speedup vs baseline: 1.6475x; 1.0313x over previous
#include <cuda_runtime.h>
#include <cuda_fp16.h>
#include <math.h>
#include <stdint.h>

#define BB 4
#define SS 2048
#define DD 1024

// ---------------- device scratch ----------------
__device__ __half g_xh[BB * SS * DD];
__device__ __half g_xc[BB * SS * DD];          // compacted (kept) rows of x, fp16
__device__ __half g_Wqh[DD * DD];
__device__ __half g_Wkvh[2 * DD * DD];         // [Wk ; Wv] concat, each [D][D]
__device__ __half g_Qh[BB * SS * DD];
__device__ __half g_Kc[BB * SS * DD];          // compacted K
__device__ __half g_Vtc[BB * SS * DD];         // compacted V, [B][D][j]
__device__ __half g_Ph[(size_t)BB * SS * SS];  // unnormalized exp(logit), fp16
__device__ float  g_rsum[BB * SS];             // per-row exp sums -> reciprocals
__device__ int    g_idx[BB * SS];
__device__ int    g_nkeep[BB];
__device__ int    g_npad[BB];

// ---------------- helpers ----------------
__device__ __forceinline__ uint32_t smem_u32(const void* p) {
    uint32_t a;
    asm("{ .reg .u64 t; cvta.to.shared.u64 t, %1; cvt.u32.u64 %0, t; }" : "=r"(a) : "l"(p));
    return a;
}
__device__ __forceinline__ void cp16(uint32_t s, const void* g) {
    asm volatile("cp.async.cg.shared.global [%0], [%1], 16;" :: "r"(s), "l"(g) : "memory");
}
#define CP_COMMIT() asm volatile("cp.async.commit_group;" ::: "memory")
#define CP_WAIT(n)  asm volatile("cp.async.wait_group %0;" :: "n"(n) : "memory")

__device__ __forceinline__ void ldm4(uint32_t* r, uint32_t a) {
    asm volatile("ldmatrix.sync.aligned.m8n8.x4.shared.b16 {%0,%1,%2,%3}, [%4];"
                 : "=r"(r[0]), "=r"(r[1]), "=r"(r[2]), "=r"(r[3]) : "r"(a));
}
__device__ __forceinline__ void mma16816(float* d, const uint32_t* a, uint32_t b0, uint32_t b1) {
    asm volatile(
        "mma.sync.aligned.m16n8k16.row.col.f32.f16.f16.f32 "
        "{%0,%1,%2,%3}, {%4,%5,%6,%7}, {%8,%9}, {%0,%1,%2,%3};"
        : "+f"(d[0]), "+f"(d[1]), "+f"(d[2]), "+f"(d[3])
        : "r"(a[0]), "r"(a[1]), "r"(a[2]), "r"(a[3]), "r"(b0), "r"(b1));
}

// ---------------------------------------------------------------------------
// Plain-fp16 NT GEMM core (round-7 config: CTA 128x128, 8 warps 64x32,
// k-tile 32, 4-stage cp.async, one __syncthreads/k-iter, 2 CTAs/SM) with
// per-batch dynamic limits (mLim / nLim CTA skip, kd dynamic K) and EPIs:
//  EPI 0: +bias, fp16 store (Q proj)
//  EPI 4: fused K|V proj: col<D -> K store; col>=D -> V transpose store
//  EPI 5: scores: Ph = exp(alpha*acc) fp16 (cols >= nkeep -> 0), rsum atomics
//  EPI 6: attn.V: fp32 store scaled by rinv[row]
// ---------------------------------------------------------------------------
static constexpr int STG    = 20480;
static constexpr int STAGES = 4;
static constexpr int SMEMB  = STAGES * STG;      // 81920

template <int EPI>
__global__ __launch_bounds__(256, 2)
void hgemm(const __half* __restrict__ Ah, const __half* __restrict__ Bh,
           const float* __restrict__ bias, const float* __restrict__ bias2,
           float* __restrict__ Cf, __half* __restrict__ Ch, __half* __restrict__ Ch2,
           float* __restrict__ rbuf, const int* __restrict__ nKeepA,
           int lda, int ldb, int ldc, int K, float alpha,
           long long sA, long long sB, long long sC,
           const int* __restrict__ mLim, const int* __restrict__ nLim,
           const int* __restrict__ kd)
{
    extern __shared__ char smem[];
    const uint32_t sbase = smem_u32(smem);
    const int t    = threadIdx.x;
    const int lane = t & 31;
    const int wid  = t >> 5;
    const int wm   = wid >> 2;
    const int wn   = wid & 3;
    const int lr   = lane & 15;
    const int lh   = lane >> 4;

    const long long bz = blockIdx.z;
    const int row0 = blockIdx.y * 128;
    const int col0 = blockIdx.x * 128;
    if (mLim && row0 >= mLim[bz]) return;
    if (nLim && col0 >= nLim[bz]) return;
    if (kd) K = kd[bz];

    Ah += bz * sA;
    Bh += bz * sB;
    if (Cf)  Cf  += bz * sC;
    if (Ch)  Ch  += bz * sC;
    if (Ch2) Ch2 += bz * sC;
    if (rbuf) rbuf += bz * SS;

    float acc[4][4][4];
#pragma unroll
    for (int i = 0; i < 4; i++)
#pragma unroll
        for (int j = 0; j < 4; j++)
#pragma unroll
            for (int r = 0; r < 4; r++) acc[i][j][r] = 0.0f;

    auto load_tile = [&](int jt, int s) {
        const uint32_t dstb = sbase + s * STG;
#pragma unroll
        for (int q = 0; q < 4; q++) {
            int idx = q * 256 + t;
            int arr = idx >> 9;
            int rem = idx & 511;
            int row = rem >> 2;
            int ch  = rem & 3;
            const __half* src = (arr == 0) ? (Ah + (size_t)(row0 + row) * lda)
                                           : (Bh + (size_t)(col0 + row) * ldb);
            src += jt * 32 + ch * 8;
            cp16(dstb + arr * 10240u + row * 80u + ch * 16u, src);
        }
    };

    auto compute = [&](uint32_t sb) {
#pragma unroll
        for (int kk = 0; kk < 32; kk += 16) {
            uint32_t ah[4][4], bh[2][4];
#pragma unroll
            for (int i = 0; i < 4; i++) {
                uint32_t ra = (uint32_t)(((wm * 64 + i * 16 + lr) * 40 + kk + 8 * lh) * 2);
                ldm4(ah[i], sb + ra);
            }
#pragma unroll
            for (int j2 = 0; j2 < 2; j2++) {
                uint32_t rb = (uint32_t)(((wn * 32 + j2 * 16 + lr) * 40 + kk + 8 * lh) * 2);
                ldm4(bh[j2], sb + 10240u + rb);
            }
#pragma unroll
            for (int i = 0; i < 4; i++)
#pragma unroll
                for (int j = 0; j < 4; j++) {
                    const int j2 = j >> 1, sl = j & 1;
                    mma16816(acc[i][j], ah[i], bh[j2][sl], bh[j2][sl + 2]);
                }
        }
    };

    const int KT = K >> 5;
    load_tile(0, 0); CP_COMMIT();
    load_tile(1, 1); CP_COMMIT();

    for (int kt = 0; kt < KT; kt++) {
        const int j = kt + 2;
        if (j < KT) load_tile(j, j & 3);
        CP_COMMIT();
        CP_WAIT(2);
        __syncthreads();
        compute(sbase + (uint32_t)((kt & 3) * STG));
    }

    // ---------------- epilogue ----------------
    const int g  = lane >> 2;
    const int tq = lane & 3;

    if (EPI == 0) {
#pragma unroll
        for (int i = 0; i < 4; i++) {
            int r0 = row0 + wm * 64 + i * 16 + g;
#pragma unroll
            for (int j = 0; j < 4; j++) {
                int c = col0 + wn * 32 + j * 8 + tq * 2;
                float bx = bias[c], by = bias[c + 1];
#pragma unroll
                for (int h = 0; h < 2; h++) {
                    float vx = acc[i][j][2 * h + 0] + bx;
                    float vy = acc[i][j][2 * h + 1] + by;
                    size_t off = (size_t)(r0 + 8 * h) * ldc + c;
                    *(__half2*)(Ch + off) =
                        __halves2half2(__float2half_rn(vx), __float2half_rn(vy));
                }
            }
        }
    } else if (EPI == 4) {
        if (col0 < DD) {
            // K path: store Kc rows, ldc = DD
#pragma unroll
            for (int i = 0; i < 4; i++) {
                int r0 = row0 + wm * 64 + i * 16 + g;
#pragma unroll
                for (int j = 0; j < 4; j++) {
                    int c = col0 + wn * 32 + j * 8 + tq * 2;
                    float bx = bias[c], by = bias[c + 1];
#pragma unroll
                    for (int h = 0; h < 2; h++) {
                        float vx = acc[i][j][2 * h + 0] + bx;
                        float vy = acc[i][j][2 * h + 1] + by;
                        size_t off = (size_t)(r0 + 8 * h) * DD + c;
                        *(__half2*)(Ch + off) =
                            __halves2half2(__float2half_rn(vx), __float2half_rn(vy));
                    }
                }
            }
        } else {
            // V path: transpose to Vtc[d][j]
            __syncthreads();
            __half* hs = (__half*)smem;             // [128][136]
            const int d0 = col0 - DD;
#pragma unroll
            for (int i = 0; i < 4; i++) {
                int m0 = wm * 64 + i * 16 + g;
#pragma unroll
                for (int j = 0; j < 4; j++) {
                    int c = wn * 32 + j * 8 + tq * 2;
                    float bx = bias2[d0 + c], by = bias2[d0 + c + 1];
#pragma unroll
                    for (int h = 0; h < 2; h++) {
                        int m = m0 + 8 * h;
                        hs[(c + 0) * 136 + m] = __float2half_rn(acc[i][j][2 * h + 0] + bx);
                        hs[(c + 1) * 136 + m] = __float2half_rn(acc[i][j][2 * h + 1] + by);
                    }
                }
            }
            __syncthreads();
            const int cb = t >> 5;
            const int m  = (t & 31) * 4;
#pragma unroll 4
            for (int cc = cb; cc < 128; cc += 8) {
                size_t off = (size_t)(d0 + cc) * SS + row0 + m;
                *(__half2*)(Ch2 + off)     = *(__half2*)(hs + cc * 136 + m);
                *(__half2*)(Ch2 + off + 2) = *(__half2*)(hs + cc * 136 + m + 2);
            }
        }
    } else if (EPI == 5) {
        // scores: e = exp(alpha*acc) for cols < nkeep, else 0; fp16 store + rsum
        const int nk = nKeepA[bz];
#pragma unroll
        for (int i = 0; i < 4; i++) {
            int r0 = row0 + wm * 64 + i * 16 + g;
            float s0 = 0.0f, s1 = 0.0f;
#pragma unroll
            for (int j = 0; j < 4; j++) {
                int c = col0 + wn * 32 + j * 8 + tq * 2;
                float e0 = (c     < nk) ? __expf(acc[i][j][0] * alpha) : 0.0f;
                float e1 = (c + 1 < nk) ? __expf(acc[i][j][1] * alpha) : 0.0f;
                float e2 = (c     < nk) ? __expf(acc[i][j][2] * alpha) : 0.0f;
                float e3 = (c + 1 < nk) ? __expf(acc[i][j][3] * alpha) : 0.0f;
                s0 += e0 + e1;
                s1 += e2 + e3;
                *(__half2*)(Ch + (size_t)r0 * SS + c) =
                    __halves2half2(__float2half_rn(e0), __float2half_rn(e1));
                *(__half2*)(Ch + (size_t)(r0 + 8) * SS + c) =
                    __halves2half2(__float2half_rn(e2), __float2half_rn(e3));
            }
            // reduce over the 4 lanes of the quad (same row), then one atomic
            s0 += __shfl_xor_sync(0xffffffffu, s0, 1);
            s0 += __shfl_xor_sync(0xffffffffu, s0, 2);
            s1 += __shfl_xor_sync(0xffffffffu, s1, 1);
            s1 += __shfl_xor_sync(0xffffffffu, s1, 2);
            if (tq == 0) {
                atomicAdd(rbuf + r0, s0);
                atomicAdd(rbuf + r0 + 8, s1);
            }
        }
    } else {  // EPI == 6 : out = acc * rinv[row]
#pragma unroll
        for (int i = 0; i < 4; i++) {
            int r0 = row0 + wm * 64 + i * 16 + g;
            float v0s = rbuf[r0], v1s = rbuf[r0 + 8];
#pragma unroll
            for (int j = 0; j < 4; j++) {
                int c = col0 + wn * 32 + j * 8 + tq * 2;
                float2 v0 = make_float2(acc[i][j][0] * v0s, acc[i][j][1] * v0s);
                float2 v1 = make_float2(acc[i][j][2] * v1s, acc[i][j][3] * v1s);
                *(float2*)(Cf + (size_t)r0 * ldc + c)       = v0;
                *(float2*)(Cf + (size_t)(r0 + 8) * ldc + c) = v1;
            }
        }
    }
}

// ---------------------------------------------------------------------------
__global__ __launch_bounds__(256)
void cvt_kernel(const float* __restrict__ in, __half* __restrict__ hi, int n4)
{
    int i = blockIdx.x * 256 + threadIdx.x;
    if (i >= n4) return;
    float4 v = ((const float4*)in)[i];
    ((__half2*)hi)[2 * i + 0] = __halves2half2(__float2half_rn(v.x), __float2half_rn(v.y));
    ((__half2*)hi)[2 * i + 1] = __halves2half2(__float2half_rn(v.z), __float2half_rn(v.w));
}

__global__ __launch_bounds__(256)
void cvt3_kernel(const float* __restrict__ w0, const float* __restrict__ w1,
                 const float* __restrict__ w2,
                 __half* __restrict__ h0, __half* __restrict__ h1,
                 __half* __restrict__ h2, int n4)
{
    int i = blockIdx.x * 256 + threadIdx.x;
    if (i >= n4) return;
    const float* in = (blockIdx.y == 0) ? w0 : (blockIdx.y == 1) ? w1 : w2;
    __half* hi = (blockIdx.y == 0) ? h0 : (blockIdx.y == 1) ? h1 : h2;
    float4 v = ((const float4*)in)[i];
    ((__half2*)hi)[2 * i + 0] = __halves2half2(__float2half_rn(v.x), __float2half_rn(v.y));
    ((__half2*)hi)[2 * i + 1] = __halves2half2(__float2half_rn(v.z), __float2half_rn(v.w));
}

// ---------------------------------------------------------------------------
// Per-batch compaction of kept key indices (ascending). One block per batch.
// ---------------------------------------------------------------------------
__global__ __launch_bounds__(256)
void compact_kernel(const int* __restrict__ mask, int* __restrict__ idx,
                    int* __restrict__ nkeepA, int* __restrict__ npadA)
{
    const int b = blockIdx.x;
    const int t = threadIdx.x;
    const int* m = mask + (size_t)b * SS;
    __shared__ int cnt[257];
    int loc[8], c = 0;
#pragma unroll
    for (int i = 0; i < 8; i++) {
        loc[i] = (m[t * 8 + i] != 0);
        c += loc[i];
    }
    cnt[t + 1] = c;
    if (t == 0) cnt[0] = 0;
    __syncthreads();
    if (t == 0)
        for (int i = 1; i <= 256; i++) cnt[i] += cnt[i - 1];
    __syncthreads();
    int base = cnt[t];
#pragma unroll
    for (int i = 0; i < 8; i++)
        if (loc[i]) idx[(size_t)b * SS + (base++)] = t * 8 + i;
    if (t == 0) {
        int tot = cnt[256];
        nkeepA[b] = tot;
        npadA[b]  = (tot + 127) & ~127;
    }
}

// Gather compacted rows directly from fp32 x (convert on the fly; zero pad).
__global__ __launch_bounds__(128)
void gather_xc(const float* __restrict__ x, const int* __restrict__ idx,
               const int* __restrict__ nkeepA, __half* __restrict__ xc)
{
    const int j = blockIdx.x, b = blockIdx.y, t = threadIdx.x;
    __half* dst = xc + ((size_t)b * SS + j) * DD + t * 8;
    if (j < nkeepA[b]) {
        const float* src = x + ((size_t)b * SS + idx[(size_t)b * SS + j]) * DD + t * 8;
        float4 a = ((const float4*)src)[0];
        float4 c = ((const float4*)src)[1];
        ((__half2*)dst)[0] = __halves2half2(__float2half_rn(a.x), __float2half_rn(a.y));
        ((__half2*)dst)[1] = __halves2half2(__float2half_rn(a.z), __float2half_rn(a.w));
        ((__half2*)dst)[2] = __halves2half2(__float2half_rn(c.x), __float2half_rn(c.y));
        ((__half2*)dst)[3] = __halves2half2(__float2half_rn(c.z), __float2half_rn(c.w));
    } else {
        uint4 z = make_uint4(0, 0, 0, 0);
        *(uint4*)dst = z;
    }
}

__global__ __launch_bounds__(1024)
void zero_kernel(float* __restrict__ p)
{
    p[blockIdx.x * 1024 + threadIdx.x] = 0.0f;
}

__global__ __launch_bounds__(1024)
void recip_kernel(float* __restrict__ p)
{
    int i = blockIdx.x * 1024 + threadIdx.x;
    p[i] = 1.0f / p[i];
}

// ---------------------------------------------------------------------------
extern "C" void kernel_launch(void* const* d_in, const int* in_sizes, int n_in,
                              void* d_out, int out_size)
{
    const float* x    = (const float*)d_in[0];
    const int*   mask = (const int*)  d_in[1];
    const float* Wq   = (const float*)d_in[2];
    const float* bq   = (const float*)d_in[3];
    const float* Wk   = (const float*)d_in[4];
    const float* bk   = (const float*)d_in[5];
    const float* Wv   = (const float*)d_in[6];
    const float* bv   = (const float*)d_in[7];
    float* out = (float*)d_out;

    __half *xh, *xc, *Wqh, *Wkvh, *Qh, *Kc, *Vtc, *Ph;
    float* rsum;
    int *idx, *nkeep, *npad;
    cudaGetSymbolAddress((void**)&xh,   g_xh);
    cudaGetSymbolAddress((void**)&xc,   g_xc);
    cudaGetSymbolAddress((void**)&Wqh,  g_Wqh);
    cudaGetSymbolAddress((void**)&Wkvh, g_Wkvh);
    cudaGetSymbolAddress((void**)&Qh,   g_Qh);
    cudaGetSymbolAddress((void**)&Kc,   g_Kc);
    cudaGetSymbolAddress((void**)&Vtc,  g_Vtc);
    cudaGetSymbolAddress((void**)&Ph,   g_Ph);
    cudaGetSymbolAddress((void**)&rsum, g_rsum);
    cudaGetSymbolAddress((void**)&idx,  g_idx);
    cudaGetSymbolAddress((void**)&nkeep, g_nkeep);
    cudaGetSymbolAddress((void**)&npad, g_npad);

    cudaFuncSetAttribute(hgemm<0>, cudaFuncAttributeMaxDynamicSharedMemorySize, SMEMB);
    cudaFuncSetAttribute(hgemm<4>, cudaFuncAttributeMaxDynamicSharedMemorySize, SMEMB);
    cudaFuncSetAttribute(hgemm<5>, cudaFuncAttributeMaxDynamicSharedMemorySize, SMEMB);
    cudaFuncSetAttribute(hgemm<6>, cudaFuncAttributeMaxDynamicSharedMemorySize, SMEMB);

    const long long sBD = (long long)SS * DD;
    const long long sSS = (long long)SS * SS;

    // #0-#4: prep
    compact_kernel<<<BB, 256>>>(mask, idx, nkeep, npad);
    zero_kernel<<<BB * SS / 1024, 1024>>>(rsum);
    cvt_kernel<<<BB * SS * DD / 4 / 256, 256>>>(x, xh, BB * SS * DD / 4);
    {
        dim3 g(DD * DD / 4 / 256, 3);
        cvt3_kernel<<<g, 256>>>(Wq, Wk, Wv, Wqh, Wkvh, Wkvh + DD * DD, DD * DD / 4);
    }
    {
        dim3 g(SS, BB);
        gather_xc<<<g, 128>>>(x, idx, nkeep, xc);
    }

    // #5 (ncu target): Q projection, full M
    {
        dim3 g(DD / 128, BB * SS / 128, 1);
        hgemm<0><<<g, 256, SMEMB>>>(xh, Wqh, bq, nullptr, nullptr, Qh, nullptr,
                                    nullptr, nullptr,
                                    DD, DD, DD, DD, 1.0f, 0, 0, 0,
                                    nullptr, nullptr, nullptr);
    }
    // #6: fused K|V projection on compacted rows
    {
        dim3 g(2 * DD / 128, SS / 128, BB);
        hgemm<4><<<g, 256, SMEMB>>>(xc, Wkvh, bk, bv, nullptr, Kc, Vtc,
                                    nullptr, nullptr,
                                    DD, DD, DD, DD, 1.0f, sBD, 0, sBD,
                                    npad, nullptr, nullptr);
    }
    // #7: scores -> unnormalized exp fp16 + row sums
    {
        dim3 g(SS / 128, SS / 128, BB);
        hgemm<5><<<g, 256, SMEMB>>>(Qh, Kc, nullptr, nullptr, nullptr, Ph, nullptr,
                                    rsum, nkeep,
                                    DD, DD, SS, DD, 1.0f / 32.0f,
                                    sBD, sBD, sSS,
                                    nullptr, npad, nullptr);
    }
    // #8: reciprocal of row sums
    recip_kernel<<<BB * SS / 1024, 1024>>>(rsum);

    // #9: out = (E @ Vtc^T) * rinv[row], dynamic K = npad[b]
    {
        dim3 g(DD / 128, SS / 128, BB);
        hgemm<6><<<g, 256, SMEMB>>>(Ph, Vtc, nullptr, nullptr, out, nullptr, nullptr,
                                    rsum, nullptr,
                                    SS, SS, DD, DD, 1.0f,
                                    sSS, sBD, sBD,
                                    nullptr, nullptr, npad);
    }
}

// round 12
// speedup vs baseline: 1.6923x; 1.0272x over previous
#include <cuda_runtime.h>
#include <cuda_fp16.h>
#include <math.h>
#include <stdint.h>

#define BB 4
#define SS 2048
#define DD 1024

// ---------------- device scratch ----------------
__device__ __half g_xh[BB * SS * DD];
__device__ __half g_xc[BB * SS * DD];          // compacted (kept) rows of x, fp16
__device__ __half g_Wqh[DD * DD];
__device__ __half g_Wkvh[2 * DD * DD];         // [Wk ; Wv] concat, each [D][D]
__device__ __half g_Qh[BB * SS * DD];
__device__ __half g_Kc[BB * SS * DD];          // compacted K
__device__ __half g_Vtc[BB * SS * DD];         // compacted V, [B][D][j]
__device__ __half g_Ph[(size_t)BB * SS * SS];  // unnormalized exp(logit), fp16
__device__ float  g_rsum[BB * SS];             // per-row exp sums
__device__ int    g_idx[BB * SS];
__device__ int    g_nkeep[BB];
__device__ int    g_npad[BB];

// ---------------- helpers ----------------
__device__ __forceinline__ uint32_t smem_u32(const void* p) {
    uint32_t a;
    asm("{ .reg .u64 t; cvta.to.shared.u64 t, %1; cvt.u32.u64 %0, t; }" : "=r"(a) : "l"(p));
    return a;
}
__device__ __forceinline__ void cp16(uint32_t s, const void* g) {
    asm volatile("cp.async.cg.shared.global [%0], [%1], 16;" :: "r"(s), "l"(g) : "memory");
}
#define CP_COMMIT() asm volatile("cp.async.commit_group;" ::: "memory")
#define CP_WAIT(n)  asm volatile("cp.async.wait_group %0;" :: "n"(n) : "memory")

__device__ __forceinline__ void ldm4(uint32_t* r, uint32_t a) {
    asm volatile("ldmatrix.sync.aligned.m8n8.x4.shared.b16 {%0,%1,%2,%3}, [%4];"
                 : "=r"(r[0]), "=r"(r[1]), "=r"(r[2]), "=r"(r[3]) : "r"(a));
}
__device__ __forceinline__ void mma16816(float* d, const uint32_t* a, uint32_t b0, uint32_t b1) {
    asm volatile(
        "mma.sync.aligned.m16n8k16.row.col.f32.f16.f16.f32 "
        "{%0,%1,%2,%3}, {%4,%5,%6,%7}, {%8,%9}, {%0,%1,%2,%3};"
        : "+f"(d[0]), "+f"(d[1]), "+f"(d[2]), "+f"(d[3])
        : "r"(a[0]), "r"(a[1]), "r"(a[2]), "r"(a[3]), "r"(b0), "r"(b1));
}

// ---------------------------------------------------------------------------
// Plain-fp16 NT GEMM core (CTA 128x128, 8 warps 64x32, k-tile 32, 4-stage
// cp.async, one __syncthreads/k-iter, 2 CTAs/SM). EPIs:
//  EPI 5: scores: Ph = exp(alpha*acc) fp16 (cols >= nkeep -> 0), rsum atomics
//  EPI 6: attn.V: fp32 store scaled by 1/rsum[row]
//  EPI 7: merged projections: bz<BB -> K|V proj on compacted rows (EPI4 style);
//         bz>=BB -> Q proj row-segment (bz-BB)*2048 (EPI0 style via qA/qB/qC)
// ---------------------------------------------------------------------------
static constexpr int STG    = 20480;
static constexpr int STAGES = 4;
static constexpr int SMEMB  = STAGES * STG;      // 81920

template <int EPI>
__global__ __launch_bounds__(256, 2)
void hgemm(const __half* __restrict__ Ah, const __half* __restrict__ Bh,
           const float* __restrict__ bias, const float* __restrict__ bias2,
           float* __restrict__ Cf, __half* __restrict__ Ch, __half* __restrict__ Ch2,
           float* __restrict__ rbuf, const int* __restrict__ nKeepA,
           int lda, int ldb, int ldc, int K, float alpha,
           long long sA, long long sB, long long sC,
           const int* __restrict__ mLim, const int* __restrict__ nLim,
           const int* __restrict__ kd,
           const __half* __restrict__ qA, const __half* __restrict__ qB,
           const float* __restrict__ qbias, __half* __restrict__ qC)
{
    extern __shared__ char smem[];
    const uint32_t sbase = smem_u32(smem);
    const int t    = threadIdx.x;
    const int lane = t & 31;
    const int wid  = t >> 5;
    const int wm   = wid >> 2;
    const int wn   = wid & 3;
    const int lr   = lane & 15;
    const int lh   = lane >> 4;

    const long long bz = blockIdx.z;
    const int row0 = blockIdx.y * 128;
    const int col0 = blockIdx.x * 128;

    bool qmode = false;
    if (EPI == 7) {
        if (bz >= BB) {
            qmode = true;
            if (col0 >= DD) return;
            Ah = qA + (size_t)(bz - BB) * 2048 * DD;
            Bh = qB;
        } else {
            if (row0 >= mLim[bz]) return;
            Ah += bz * sA;
            // Bh: weights, no batch offset
        }
    } else {
        if (mLim && row0 >= mLim[bz]) return;
        if (nLim && col0 >= nLim[bz]) return;
        if (kd) K = kd[bz];
        Ah += bz * sA;
        Bh += bz * sB;
        if (Cf)  Cf  += bz * sC;
        if (Ch)  Ch  += bz * sC;
        if (rbuf) rbuf += bz * SS;
    }

    float acc[4][4][4];
#pragma unroll
    for (int i = 0; i < 4; i++)
#pragma unroll
        for (int j = 0; j < 4; j++)
#pragma unroll
            for (int r = 0; r < 4; r++) acc[i][j][r] = 0.0f;

    auto load_tile = [&](int jt, int s) {
        const uint32_t dstb = sbase + s * STG;
#pragma unroll
        for (int q = 0; q < 4; q++) {
            int idx = q * 256 + t;
            int arr = idx >> 9;
            int rem = idx & 511;
            int row = rem >> 2;
            int ch  = rem & 3;
            const __half* src = (arr == 0) ? (Ah + (size_t)(row0 + row) * lda)
                                           : (Bh + (size_t)(col0 + row) * ldb);
            src += jt * 32 + ch * 8;
            cp16(dstb + arr * 10240u + row * 80u + ch * 16u, src);
        }
    };

    auto compute = [&](uint32_t sb) {
#pragma unroll
        for (int kk = 0; kk < 32; kk += 16) {
            uint32_t ah[4][4], bh[2][4];
#pragma unroll
            for (int i = 0; i < 4; i++) {
                uint32_t ra = (uint32_t)(((wm * 64 + i * 16 + lr) * 40 + kk + 8 * lh) * 2);
                ldm4(ah[i], sb + ra);
            }
#pragma unroll
            for (int j2 = 0; j2 < 2; j2++) {
                uint32_t rb = (uint32_t)(((wn * 32 + j2 * 16 + lr) * 40 + kk + 8 * lh) * 2);
                ldm4(bh[j2], sb + 10240u + rb);
            }
#pragma unroll
            for (int i = 0; i < 4; i++)
#pragma unroll
                for (int j = 0; j < 4; j++) {
                    const int j2 = j >> 1, sl = j & 1;
                    mma16816(acc[i][j], ah[i], bh[j2][sl], bh[j2][sl + 2]);
                }
        }
    };

    const int KT = K >> 5;
    load_tile(0, 0); CP_COMMIT();
    load_tile(1, 1); CP_COMMIT();

    for (int kt = 0; kt < KT; kt++) {
        const int j = kt + 2;
        if (j < KT) load_tile(j, j & 3);
        CP_COMMIT();
        CP_WAIT(2);
        __syncthreads();
        compute(sbase + (uint32_t)((kt & 3) * STG));
    }

    // ---------------- epilogue ----------------
    const int g  = lane >> 2;
    const int tq = lane & 3;

    if (EPI == 7) {
        if (qmode) {
            __half* C = qC + (size_t)(bz - BB) * 2048 * DD;
#pragma unroll
            for (int i = 0; i < 4; i++) {
                int r0 = row0 + wm * 64 + i * 16 + g;
#pragma unroll
                for (int j = 0; j < 4; j++) {
                    int c = col0 + wn * 32 + j * 8 + tq * 2;
                    float bx = qbias[c], by = qbias[c + 1];
#pragma unroll
                    for (int h = 0; h < 2; h++) {
                        float vx = acc[i][j][2 * h + 0] + bx;
                        float vy = acc[i][j][2 * h + 1] + by;
                        size_t off = (size_t)(r0 + 8 * h) * DD + c;
                        *(__half2*)(C + off) =
                            __halves2half2(__float2half_rn(vx), __float2half_rn(vy));
                    }
                }
            }
        } else if (col0 < DD) {
            // K path
            __half* C = Ch + bz * sC;
#pragma unroll
            for (int i = 0; i < 4; i++) {
                int r0 = row0 + wm * 64 + i * 16 + g;
#pragma unroll
                for (int j = 0; j < 4; j++) {
                    int c = col0 + wn * 32 + j * 8 + tq * 2;
                    float bx = bias[c], by = bias[c + 1];
#pragma unroll
                    for (int h = 0; h < 2; h++) {
                        float vx = acc[i][j][2 * h + 0] + bx;
                        float vy = acc[i][j][2 * h + 1] + by;
                        size_t off = (size_t)(r0 + 8 * h) * DD + c;
                        *(__half2*)(C + off) =
                            __halves2half2(__float2half_rn(vx), __float2half_rn(vy));
                    }
                }
            }
        } else {
            // V path: transpose to Vtc[d][j]
            __syncthreads();
            __half* hs = (__half*)smem;             // [128][136]
            const int d0 = col0 - DD;
            __half* C2 = Ch2 + bz * sC;
#pragma unroll
            for (int i = 0; i < 4; i++) {
                int m0 = wm * 64 + i * 16 + g;
#pragma unroll
                for (int j = 0; j < 4; j++) {
                    int c = wn * 32 + j * 8 + tq * 2;
                    float bx = bias2[d0 + c], by = bias2[d0 + c + 1];
#pragma unroll
                    for (int h = 0; h < 2; h++) {
                        int m = m0 + 8 * h;
                        hs[(c + 0) * 136 + m] = __float2half_rn(acc[i][j][2 * h + 0] + bx);
                        hs[(c + 1) * 136 + m] = __float2half_rn(acc[i][j][2 * h + 1] + by);
                    }
                }
            }
            __syncthreads();
            const int cb = t >> 5;
            const int m  = (t & 31) * 4;
#pragma unroll 4
            for (int cc = cb; cc < 128; cc += 8) {
                size_t off = (size_t)(d0 + cc) * SS + row0 + m;
                *(__half2*)(C2 + off)     = *(__half2*)(hs + cc * 136 + m);
                *(__half2*)(C2 + off + 2) = *(__half2*)(hs + cc * 136 + m + 2);
            }
        }
    } else if (EPI == 5) {
        const int nk = nKeepA[bz];
#pragma unroll
        for (int i = 0; i < 4; i++) {
            int r0 = row0 + wm * 64 + i * 16 + g;
            float s0 = 0.0f, s1 = 0.0f;
#pragma unroll
            for (int j = 0; j < 4; j++) {
                int c = col0 + wn * 32 + j * 8 + tq * 2;
                float e0 = (c     < nk) ? __expf(acc[i][j][0] * alpha) : 0.0f;
                float e1 = (c + 1 < nk) ? __expf(acc[i][j][1] * alpha) : 0.0f;
                float e2 = (c     < nk) ? __expf(acc[i][j][2] * alpha) : 0.0f;
                float e3 = (c + 1 < nk) ? __expf(acc[i][j][3] * alpha) : 0.0f;
                s0 += e0 + e1;
                s1 += e2 + e3;
                *(__half2*)(Ch + (size_t)r0 * SS + c) =
                    __halves2half2(__float2half_rn(e0), __float2half_rn(e1));
                *(__half2*)(Ch + (size_t)(r0 + 8) * SS + c) =
                    __halves2half2(__float2half_rn(e2), __float2half_rn(e3));
            }
            s0 += __shfl_xor_sync(0xffffffffu, s0, 1);
            s0 += __shfl_xor_sync(0xffffffffu, s0, 2);
            s1 += __shfl_xor_sync(0xffffffffu, s1, 1);
            s1 += __shfl_xor_sync(0xffffffffu, s1, 2);
            if (tq == 0) {
                atomicAdd(rbuf + r0, s0);
                atomicAdd(rbuf + r0 + 8, s1);
            }
        }
    } else {  // EPI == 6 : out = acc / rsum[row]
#pragma unroll
        for (int i = 0; i < 4; i++) {
            int r0 = row0 + wm * 64 + i * 16 + g;
            float v0s = 1.0f / rbuf[r0];
            float v1s = 1.0f / rbuf[r0 + 8];
#pragma unroll
            for (int j = 0; j < 4; j++) {
                int c = col0 + wn * 32 + j * 8 + tq * 2;
                float2 v0 = make_float2(acc[i][j][0] * v0s, acc[i][j][1] * v0s);
                float2 v1 = make_float2(acc[i][j][2] * v1s, acc[i][j][3] * v1s);
                *(float2*)(Cf + (size_t)r0 * ldc + c)       = v0;
                *(float2*)(Cf + (size_t)(r0 + 8) * ldc + c) = v1;
            }
        }
    }
}

// ---------------------------------------------------------------------------
// prep1: per-batch key compaction + zero rsum. One block per batch.
// ---------------------------------------------------------------------------
__global__ __launch_bounds__(256)
void prep1_kernel(const int* __restrict__ mask, int* __restrict__ idx,
                  int* __restrict__ nkeepA, int* __restrict__ npadA,
                  float* __restrict__ rsum)
{
    const int b = blockIdx.x;
    const int t = threadIdx.x;
    const int* m = mask + (size_t)b * SS;
    __shared__ int cnt[257];
    int loc[8], c = 0;
#pragma unroll
    for (int i = 0; i < 8; i++) {
        loc[i] = (m[t * 8 + i] != 0);
        c += loc[i];
    }
    cnt[t + 1] = c;
    if (t == 0) cnt[0] = 0;
    __syncthreads();
    if (t == 0)
        for (int i = 1; i <= 256; i++) cnt[i] += cnt[i - 1];
    __syncthreads();
    int base = cnt[t];
#pragma unroll
    for (int i = 0; i < 8; i++)
        if (loc[i]) idx[(size_t)b * SS + (base++)] = t * 8 + i;
    if (t == 0) {
        int tot = cnt[256];
        nkeepA[b] = tot;
        npadA[b]  = (tot + 127) & ~127;
    }
    // zero rsum (8192 floats / 1024 threads = 2 float4 each)
    float4 z = make_float4(0.f, 0.f, 0.f, 0.f);
    ((float4*)rsum)[(b * 256 + t) * 2 + 0] = z;
    ((float4*)rsum)[(b * 256 + t) * 2 + 1] = z;
}

// ---------------------------------------------------------------------------
// prep2: y<BB -> gather compacted row (fp32->fp16, zero pad);
//        y>=BB -> grid-stride fp32->fp16 convert of x + 3 weight matrices.
// grid (SS, BB+2), 128 threads.
// ---------------------------------------------------------------------------
static constexpr int CVT_F4 = 2883584;           // (8M + 3M) / 4
__global__ __launch_bounds__(128)
void prep2_kernel(const float* __restrict__ x, const int* __restrict__ idx,
                  const int* __restrict__ nkeepA, __half* __restrict__ xc,
                  const float* __restrict__ Wq, const float* __restrict__ Wk,
                  const float* __restrict__ Wv,
                  __half* __restrict__ xh, __half* __restrict__ Wqh,
                  __half* __restrict__ Wkvh)
{
    const int t = threadIdx.x;
    if (blockIdx.y < BB) {
        const int j = blockIdx.x, b = blockIdx.y;
        __half* dst = xc + ((size_t)b * SS + j) * DD + t * 8;
        if (j < nkeepA[b]) {
            const float* src = x + ((size_t)b * SS + idx[(size_t)b * SS + j]) * DD + t * 8;
            float4 a = ((const float4*)src)[0];
            float4 c = ((const float4*)src)[1];
            ((__half2*)dst)[0] = __halves2half2(__float2half_rn(a.x), __float2half_rn(a.y));
            ((__half2*)dst)[1] = __halves2half2(__float2half_rn(a.z), __float2half_rn(a.w));
            ((__half2*)dst)[2] = __halves2half2(__float2half_rn(c.x), __float2half_rn(c.y));
            ((__half2*)dst)[3] = __halves2half2(__float2half_rn(c.z), __float2half_rn(c.w));
        } else {
            *(uint4*)dst = make_uint4(0, 0, 0, 0);
        }
    } else {
        const int c = (blockIdx.y - BB) * gridDim.x + blockIdx.x;   // 0..4095
        for (int i = c * 128 + t; i < CVT_F4; i += 4096 * 128) {
            const float* src;
            __half* dst;
            int k;
            if (i < 2097152) { src = x; dst = xh; k = i; }
            else {
                int j = i - 2097152;
                int w = j >> 18;
                k = j & 262143;
                src = (w == 0) ? Wq : (w == 1) ? Wk : Wv;
                dst = (w == 0) ? Wqh : (w == 1) ? Wkvh : (Wkvh + DD * DD);
            }
            float4 v = ((const float4*)src)[k];
            ((__half2*)dst)[2 * k + 0] =
                __halves2half2(__float2half_rn(v.x), __float2half_rn(v.y));
            ((__half2*)dst)[2 * k + 1] =
                __halves2half2(__float2half_rn(v.z), __float2half_rn(v.w));
        }
    }
}

// ---------------------------------------------------------------------------
extern "C" void kernel_launch(void* const* d_in, const int* in_sizes, int n_in,
                              void* d_out, int out_size)
{
    const float* x    = (const float*)d_in[0];
    const int*   mask = (const int*)  d_in[1];
    const float* Wq   = (const float*)d_in[2];
    const float* bq   = (const float*)d_in[3];
    const float* Wk   = (const float*)d_in[4];
    const float* bk   = (const float*)d_in[5];
    const float* Wv   = (const float*)d_in[6];
    const float* bv   = (const float*)d_in[7];
    float* out = (float*)d_out;

    __half *xh, *xc, *Wqh, *Wkvh, *Qh, *Kc, *Vtc, *Ph;
    float* rsum;
    int *idx, *nkeep, *npad;
    cudaGetSymbolAddress((void**)&xh,   g_xh);
    cudaGetSymbolAddress((void**)&xc,   g_xc);
    cudaGetSymbolAddress((void**)&Wqh,  g_Wqh);
    cudaGetSymbolAddress((void**)&Wkvh, g_Wkvh);
    cudaGetSymbolAddress((void**)&Qh,   g_Qh);
    cudaGetSymbolAddress((void**)&Kc,   g_Kc);
    cudaGetSymbolAddress((void**)&Vtc,  g_Vtc);
    cudaGetSymbolAddress((void**)&Ph,   g_Ph);
    cudaGetSymbolAddress((void**)&rsum, g_rsum);
    cudaGetSymbolAddress((void**)&idx,  g_idx);
    cudaGetSymbolAddress((void**)&nkeep, g_nkeep);
    cudaGetSymbolAddress((void**)&npad, g_npad);

    cudaFuncSetAttribute(hgemm<5>, cudaFuncAttributeMaxDynamicSharedMemorySize, SMEMB);
    cudaFuncSetAttribute(hgemm<6>, cudaFuncAttributeMaxDynamicSharedMemorySize, SMEMB);
    cudaFuncSetAttribute(hgemm<7>, cudaFuncAttributeMaxDynamicSharedMemorySize, SMEMB);

    const long long sBD = (long long)SS * DD;
    const long long sSS = (long long)SS * SS;

    // #0: compaction + rsum zero
    prep1_kernel<<<BB, 256>>>(mask, idx, nkeep, npad, rsum);

    // #1: converts + gather
    {
        dim3 g(SS, BB + 2);
        prep2_kernel<<<g, 128>>>(x, idx, nkeep, xc, Wq, Wk, Wv, xh, Wqh, Wkvh);
    }

    // #2: merged Q + K|V projections
    //   z in [0,4): K|V proj batch z (cols 0..2048, rows < npad[z])
    //   z in [4,8): Q proj rows (z-4)*2048.. (cols < 1024)
    {
        dim3 g(2 * DD / 128, SS / 128, 2 * BB);
        hgemm<7><<<g, 256, SMEMB>>>(xc, Wkvh, bk, bv, nullptr, Kc, Vtc,
                                    nullptr, nullptr,
                                    DD, DD, DD, DD, 1.0f, sBD, 0, sBD,
                                    npad, nullptr, nullptr,
                                    xh, Wqh, bq, Qh);
    }

    // #3: scores -> unnormalized exp fp16 + row sums
    {
        dim3 g(SS / 128, SS / 128, BB);
        hgemm<5><<<g, 256, SMEMB>>>(Qh, Kc, nullptr, nullptr, nullptr, Ph, nullptr,
                                    rsum, nkeep,
                                    DD, DD, SS, DD, 1.0f / 32.0f,
                                    sBD, sBD, sSS,
                                    nullptr, npad, nullptr,
                                    nullptr, nullptr, nullptr, nullptr);
    }

    // #4: out = (E @ Vtc^T) / rsum[row], dynamic K = npad[b]
    {
        dim3 g(DD / 128, SS / 128, BB);
        hgemm<6><<<g, 256, SMEMB>>>(Ph, Vtc, nullptr, nullptr, out, nullptr, nullptr,
                                    rsum, nullptr,
                                    SS, SS, DD, DD, 1.0f,
                                    sSS, sBD, sBD,
                                    nullptr, nullptr, npad,
                                    nullptr, nullptr, nullptr, nullptr);
    }
}

// round 13
// speedup vs baseline: 1.8734x; 1.1070x over previous
#include <cuda_runtime.h>
#include <cuda_fp16.h>
#include <math.h>
#include <stdint.h>

#define BB 4
#define SS 2048
#define DD 1024

// ---------------- device scratch ----------------
__device__ __half g_xh[BB * SS * DD];
__device__ __half g_Wqh[DD * DD];
__device__ __half g_Wkvh[2 * DD * DD];         // [Wk ; Wv] concat
__device__ __half g_Qh[BB * SS * DD];
__device__ __half g_Kc[BB * SS * DD];          // compacted K
__device__ __half g_Vtc[BB * SS * DD];         // compacted V, [B][D][j]
__device__ __half g_Ph[(size_t)BB * SS * SS];  // unnormalized exp(logit), fp16
__device__ float  g_rsum[BB * SS];
__device__ int    g_idx[BB * SS];              // kept-row indices, padded with 0
__device__ int    g_nkeep[BB];
__device__ int    g_npad[BB];                  // 128-aligned (CTA skip)
__device__ int    g_kd32[BB];                  // 32-aligned (attn.V K-dim)

// ---------------- helpers ----------------
__device__ __forceinline__ uint32_t smem_u32(const void* p) {
    uint32_t a;
    asm("{ .reg .u64 t; cvta.to.shared.u64 t, %1; cvt.u32.u64 %0, t; }" : "=r"(a) : "l"(p));
    return a;
}
__device__ __forceinline__ void cp16(uint32_t s, const void* g) {
    asm volatile("cp.async.cg.shared.global [%0], [%1], 16;" :: "r"(s), "l"(g) : "memory");
}
#define CP_COMMIT() asm volatile("cp.async.commit_group;" ::: "memory")
#define CP_WAIT(n)  asm volatile("cp.async.wait_group %0;" :: "n"(n) : "memory")

__device__ __forceinline__ void ldm4(uint32_t* r, uint32_t a) {
    asm volatile("ldmatrix.sync.aligned.m8n8.x4.shared.b16 {%0,%1,%2,%3}, [%4];"
                 : "=r"(r[0]), "=r"(r[1]), "=r"(r[2]), "=r"(r[3]) : "r"(a));
}
__device__ __forceinline__ void mma16816(float* d, const uint32_t* a, uint32_t b0, uint32_t b1) {
    asm volatile(
        "mma.sync.aligned.m16n8k16.row.col.f32.f16.f16.f32 "
        "{%0,%1,%2,%3}, {%4,%5,%6,%7}, {%8,%9}, {%0,%1,%2,%3};"
        : "+f"(d[0]), "+f"(d[1]), "+f"(d[2]), "+f"(d[3])
        : "r"(a[0]), "r"(a[1]), "r"(a[2]), "r"(a[3]), "r"(b0), "r"(b1));
}

// ---------------------------------------------------------------------------
// Plain-fp16 NT GEMM core (CTA 128x128, 8 warps 64x32, k-tile 32, 4-stage
// cp.async, one __syncthreads/k-iter, 2 CTAs/SM). Per-thread load pointers
// hoisted out of the mainloop. EPIs:
//  EPI 5: scores: Ph = exp(alpha*acc) fp16 (cols >= nkeep -> 0), rsum atomics
//  EPI 6: attn.V: fp32 store scaled by 1/rsum[row]
//  EPI 7: merged projections: bz<BB -> K|V proj, A rows gathered via gidx;
//         bz>=BB -> Q proj row-segment (bz-BB)*2048
// ---------------------------------------------------------------------------
static constexpr int STG    = 20480;
static constexpr int STAGES = 4;
static constexpr int SMEMB  = STAGES * STG;      // 81920

template <int EPI>
__global__ __launch_bounds__(256, 2)
void hgemm(const __half* __restrict__ Ah, const __half* __restrict__ Bh,
           const float* __restrict__ bias, const float* __restrict__ bias2,
           float* __restrict__ Cf, __half* __restrict__ Ch, __half* __restrict__ Ch2,
           float* __restrict__ rbuf, const int* __restrict__ nKeepA,
           int lda, int ldb, int ldc, int K, float alpha,
           long long sA, long long sB, long long sC,
           const int* __restrict__ mLim, const int* __restrict__ nLim,
           const int* __restrict__ kd, const int* __restrict__ gidx,
           const __half* __restrict__ qA, const __half* __restrict__ qB,
           const float* __restrict__ qbias, __half* __restrict__ qC)
{
    extern __shared__ char smem[];
    const uint32_t sbase = smem_u32(smem);
    const int t    = threadIdx.x;
    const int lane = t & 31;
    const int wid  = t >> 5;
    const int wm   = wid >> 2;
    const int wn   = wid & 3;
    const int lr   = lane & 15;
    const int lh   = lane >> 4;

    const long long bz = blockIdx.z;
    const int row0 = blockIdx.y * 128;
    const int col0 = blockIdx.x * 128;

    bool qmode = false;
    if (EPI == 7) {
        if (bz >= BB) {
            qmode = true;
            if (col0 >= DD) return;
            Ah = qA + (size_t)(bz - BB) * 2048 * DD;
            Bh = qB;
        } else {
            if (row0 >= mLim[bz]) return;
            Ah += bz * sA;
        }
    } else {
        if (mLim && row0 >= mLim[bz]) return;
        if (nLim && col0 >= nLim[bz]) return;
        if (kd) K = kd[bz];
        Ah += bz * sA;
        Bh += bz * sB;
        if (Cf)  Cf  += bz * sC;
        if (Ch)  Ch  += bz * sC;
        if (rbuf) rbuf += bz * SS;
    }

    // ---- hoisted per-thread load pointers ----
    const int ch = t & 3;
    const int rr = t >> 2;               // 0..63
    int ar0 = row0 + rr, ar1 = row0 + 64 + rr;
    if (EPI == 7 && !qmode) {
        const int* ib = gidx + bz * SS;
        ar0 = ib[ar0];
        ar1 = ib[ar1];
    }
    const __half* ap0 = Ah + (size_t)ar0 * lda + ch * 8;
    const __half* ap1 = Ah + (size_t)ar1 * lda + ch * 8;
    const __half* bp0 = Bh + (size_t)(col0 + rr) * ldb + ch * 8;
    const __half* bp1 = Bh + (size_t)(col0 + 64 + rr) * ldb + ch * 8;
    const uint32_t so0 = (uint32_t)(rr * 80 + ch * 16);
    const uint32_t so1 = (uint32_t)((64 + rr) * 80 + ch * 16);

    float acc[4][4][4];
#pragma unroll
    for (int i = 0; i < 4; i++)
#pragma unroll
        for (int j = 0; j < 4; j++)
#pragma unroll
            for (int r = 0; r < 4; r++) acc[i][j][r] = 0.0f;

    auto load_tile = [&](int jt, int s) {
        const uint32_t dstb = sbase + s * STG;
        const int o = jt * 32;
        cp16(dstb + so0,          ap0 + o);
        cp16(dstb + so1,          ap1 + o);
        cp16(dstb + 10240u + so0, bp0 + o);
        cp16(dstb + 10240u + so1, bp1 + o);
    };

    auto compute = [&](uint32_t sb) {
#pragma unroll
        for (int kk = 0; kk < 32; kk += 16) {
            uint32_t ah[4][4], bh[2][4];
#pragma unroll
            for (int i = 0; i < 4; i++) {
                uint32_t ra = (uint32_t)(((wm * 64 + i * 16 + lr) * 40 + kk + 8 * lh) * 2);
                ldm4(ah[i], sb + ra);
            }
#pragma unroll
            for (int j2 = 0; j2 < 2; j2++) {
                uint32_t rb = (uint32_t)(((wn * 32 + j2 * 16 + lr) * 40 + kk + 8 * lh) * 2);
                ldm4(bh[j2], sb + 10240u + rb);
            }
#pragma unroll
            for (int i = 0; i < 4; i++)
#pragma unroll
                for (int j = 0; j < 4; j++) {
                    const int j2 = j >> 1, sl = j & 1;
                    mma16816(acc[i][j], ah[i], bh[j2][sl], bh[j2][sl + 2]);
                }
        }
    };

    const int KT = K >> 5;
    load_tile(0, 0); CP_COMMIT();
    load_tile(1, 1); CP_COMMIT();

    for (int kt = 0; kt < KT; kt++) {
        const int j = kt + 2;
        if (j < KT) load_tile(j, j & 3);
        CP_COMMIT();
        CP_WAIT(2);
        __syncthreads();
        compute(sbase + (uint32_t)((kt & 3) * STG));
    }

    // ---------------- epilogue ----------------
    const int g  = lane >> 2;
    const int tq = lane & 3;

    if (EPI == 7) {
        if (qmode) {
            __half* C = qC + (size_t)(bz - BB) * 2048 * DD;
#pragma unroll
            for (int i = 0; i < 4; i++) {
                int r0 = row0 + wm * 64 + i * 16 + g;
#pragma unroll
                for (int j = 0; j < 4; j++) {
                    int c = col0 + wn * 32 + j * 8 + tq * 2;
                    float bx = qbias[c], by = qbias[c + 1];
#pragma unroll
                    for (int h = 0; h < 2; h++) {
                        float vx = acc[i][j][2 * h + 0] + bx;
                        float vy = acc[i][j][2 * h + 1] + by;
                        size_t off = (size_t)(r0 + 8 * h) * DD + c;
                        *(__half2*)(C + off) =
                            __halves2half2(__float2half_rn(vx), __float2half_rn(vy));
                    }
                }
            }
        } else if (col0 < DD) {
            // K path
            __half* C = Ch + bz * sC;
#pragma unroll
            for (int i = 0; i < 4; i++) {
                int r0 = row0 + wm * 64 + i * 16 + g;
#pragma unroll
                for (int j = 0; j < 4; j++) {
                    int c = col0 + wn * 32 + j * 8 + tq * 2;
                    float bx = bias[c], by = bias[c + 1];
#pragma unroll
                    for (int h = 0; h < 2; h++) {
                        float vx = acc[i][j][2 * h + 0] + bx;
                        float vy = acc[i][j][2 * h + 1] + by;
                        size_t off = (size_t)(r0 + 8 * h) * DD + c;
                        *(__half2*)(C + off) =
                            __halves2half2(__float2half_rn(vx), __float2half_rn(vy));
                    }
                }
            }
        } else {
            // V path: transpose to Vtc[d][j]
            __syncthreads();
            __half* hs = (__half*)smem;             // [128][136]
            const int d0 = col0 - DD;
            __half* C2 = Ch2 + bz * sC;
#pragma unroll
            for (int i = 0; i < 4; i++) {
                int m0 = wm * 64 + i * 16 + g;
#pragma unroll
                for (int j = 0; j < 4; j++) {
                    int c = wn * 32 + j * 8 + tq * 2;
                    float bx = bias2[d0 + c], by = bias2[d0 + c + 1];
#pragma unroll
                    for (int h = 0; h < 2; h++) {
                        int m = m0 + 8 * h;
                        hs[(c + 0) * 136 + m] = __float2half_rn(acc[i][j][2 * h + 0] + bx);
                        hs[(c + 1) * 136 + m] = __float2half_rn(acc[i][j][2 * h + 1] + by);
                    }
                }
            }
            __syncthreads();
            const int cb = t >> 5;
            const int m  = (t & 31) * 4;
#pragma unroll 4
            for (int cc = cb; cc < 128; cc += 8) {
                size_t off = (size_t)(d0 + cc) * SS + row0 + m;
                *(__half2*)(C2 + off)     = *(__half2*)(hs + cc * 136 + m);
                *(__half2*)(C2 + off + 2) = *(__half2*)(hs + cc * 136 + m + 2);
            }
        }
    } else if (EPI == 5) {
        const int nk = nKeepA[bz];
#pragma unroll
        for (int i = 0; i < 4; i++) {
            int r0 = row0 + wm * 64 + i * 16 + g;
            float s0 = 0.0f, s1 = 0.0f;
#pragma unroll
            for (int j = 0; j < 4; j++) {
                int c = col0 + wn * 32 + j * 8 + tq * 2;
                float e0 = (c     < nk) ? __expf(acc[i][j][0] * alpha) : 0.0f;
                float e1 = (c + 1 < nk) ? __expf(acc[i][j][1] * alpha) : 0.0f;
                float e2 = (c     < nk) ? __expf(acc[i][j][2] * alpha) : 0.0f;
                float e3 = (c + 1 < nk) ? __expf(acc[i][j][3] * alpha) : 0.0f;
                s0 += e0 + e1;
                s1 += e2 + e3;
                *(__half2*)(Ch + (size_t)r0 * SS + c) =
                    __halves2half2(__float2half_rn(e0), __float2half_rn(e1));
                *(__half2*)(Ch + (size_t)(r0 + 8) * SS + c) =
                    __halves2half2(__float2half_rn(e2), __float2half_rn(e3));
            }
            s0 += __shfl_xor_sync(0xffffffffu, s0, 1);
            s0 += __shfl_xor_sync(0xffffffffu, s0, 2);
            s1 += __shfl_xor_sync(0xffffffffu, s1, 1);
            s1 += __shfl_xor_sync(0xffffffffu, s1, 2);
            if (tq == 0) {
                atomicAdd(rbuf + r0, s0);
                atomicAdd(rbuf + r0 + 8, s1);
            }
        }
    } else {  // EPI == 6 : out = acc / rsum[row]
#pragma unroll
        for (int i = 0; i < 4; i++) {
            int r0 = row0 + wm * 64 + i * 16 + g;
            float v0s = 1.0f / rbuf[r0];
            float v1s = 1.0f / rbuf[r0 + 8];
#pragma unroll
            for (int j = 0; j < 4; j++) {
                int c = col0 + wn * 32 + j * 8 + tq * 2;
                float2 v0 = make_float2(acc[i][j][0] * v0s, acc[i][j][1] * v0s);
                float2 v1 = make_float2(acc[i][j][2] * v1s, acc[i][j][3] * v1s);
                *(float2*)(Cf + (size_t)r0 * ldc + c)       = v0;
                *(float2*)(Cf + (size_t)(r0 + 8) * ldc + c) = v1;
            }
        }
    }
}

// ---------------------------------------------------------------------------
// Single prep kernel:
//  blocks 0..BB-1 : per-batch compaction (+ idx pad with 0, rsum zero,
//                   npad/kd32 computation)
//  blocks >= BB   : grid-stride fp32->fp16 convert of x + 3 weight matrices
// ---------------------------------------------------------------------------
static constexpr int CVT_F4   = 2883584;         // (8M + 3M) / 4
static constexpr int PREP_CVT = 1024;            // convert blocks

__global__ __launch_bounds__(256)
void prep_kernel(const int* __restrict__ mask, int* __restrict__ idx,
                 int* __restrict__ nkeepA, int* __restrict__ npadA,
                 int* __restrict__ kd32A, float* __restrict__ rsum,
                 const float* __restrict__ x,
                 const float* __restrict__ Wq, const float* __restrict__ Wk,
                 const float* __restrict__ Wv,
                 __half* __restrict__ xh, __half* __restrict__ Wqh,
                 __half* __restrict__ Wkvh)
{
    const int t = threadIdx.x;
    if (blockIdx.x < BB) {
        const int b = blockIdx.x;
        const int* m = mask + (size_t)b * SS;
        int* idxb = idx + (size_t)b * SS;
        __shared__ int cnt[257];
        int loc[8], c = 0;
#pragma unroll
        for (int i = 0; i < 8; i++) {
            loc[i] = (m[t * 8 + i] != 0);
            c += loc[i];
        }
        cnt[t + 1] = c;
        if (t == 0) cnt[0] = 0;
        __syncthreads();
        if (t == 0)
            for (int i = 1; i <= 256; i++) cnt[i] += cnt[i - 1];
        __syncthreads();
        int base = cnt[t];
#pragma unroll
        for (int i = 0; i < 8; i++)
            if (loc[i]) idxb[base++] = t * 8 + i;
        const int tot = cnt[256];
        // pad remaining index slots with 0 (any finite row works: its K/V
        // values are multiplied by exactly-zero probabilities)
        for (int i = tot + t; i < SS; i += 256) idxb[i] = 0;
        if (t == 0) {
            nkeepA[b] = tot;
            npadA[b]  = (tot + 127) & ~127;
            kd32A[b]  = (tot + 31) & ~31;
        }
        // zero rsum slice (2048 floats / 256 threads = 2 float4 each)
        float4 z = make_float4(0.f, 0.f, 0.f, 0.f);
        ((float4*)rsum)[(b * 256 + t) * 2 + 0] = z;
        ((float4*)rsum)[(b * 256 + t) * 2 + 1] = z;
    } else {
        const int cblk = blockIdx.x - BB;
        for (int i = cblk * 256 + t; i < CVT_F4; i += PREP_CVT * 256) {
            const float* src;
            __half* dst;
            int k;
            if (i < 2097152) { src = x; dst = xh; k = i; }
            else {
                int j = i - 2097152;
                int w = j >> 18;
                k = j & 262143;
                src = (w == 0) ? Wq : (w == 1) ? Wk : Wv;
                dst = (w == 0) ? Wqh : (w == 1) ? Wkvh : (Wkvh + DD * DD);
            }
            float4 v = ((const float4*)src)[k];
            ((__half2*)dst)[2 * k + 0] =
                __halves2half2(__float2half_rn(v.x), __float2half_rn(v.y));
            ((__half2*)dst)[2 * k + 1] =
                __halves2half2(__float2half_rn(v.z), __float2half_rn(v.w));
        }
    }
}

// ---------------------------------------------------------------------------
extern "C" void kernel_launch(void* const* d_in, const int* in_sizes, int n_in,
                              void* d_out, int out_size)
{
    const float* x    = (const float*)d_in[0];
    const int*   mask = (const int*)  d_in[1];
    const float* Wq   = (const float*)d_in[2];
    const float* bq   = (const float*)d_in[3];
    const float* Wk   = (const float*)d_in[4];
    const float* bk   = (const float*)d_in[5];
    const float* Wv   = (const float*)d_in[6];
    const float* bv   = (const float*)d_in[7];
    float* out = (float*)d_out;

    __half *xh, *Wqh, *Wkvh, *Qh, *Kc, *Vtc, *Ph;
    float* rsum;
    int *idx, *nkeep, *npad, *kd32;
    cudaGetSymbolAddress((void**)&xh,   g_xh);
    cudaGetSymbolAddress((void**)&Wqh,  g_Wqh);
    cudaGetSymbolAddress((void**)&Wkvh, g_Wkvh);
    cudaGetSymbolAddress((void**)&Qh,   g_Qh);
    cudaGetSymbolAddress((void**)&Kc,   g_Kc);
    cudaGetSymbolAddress((void**)&Vtc,  g_Vtc);
    cudaGetSymbolAddress((void**)&Ph,   g_Ph);
    cudaGetSymbolAddress((void**)&rsum, g_rsum);
    cudaGetSymbolAddress((void**)&idx,  g_idx);
    cudaGetSymbolAddress((void**)&nkeep, g_nkeep);
    cudaGetSymbolAddress((void**)&npad, g_npad);
    cudaGetSymbolAddress((void**)&kd32, g_kd32);

    cudaFuncSetAttribute(hgemm<5>, cudaFuncAttributeMaxDynamicSharedMemorySize, SMEMB);
    cudaFuncSetAttribute(hgemm<6>, cudaFuncAttributeMaxDynamicSharedMemorySize, SMEMB);
    cudaFuncSetAttribute(hgemm<7>, cudaFuncAttributeMaxDynamicSharedMemorySize, SMEMB);

    const long long sBD = (long long)SS * DD;
    const long long sSS = (long long)SS * SS;

    // #0: compaction + rsum zero + converts (one launch)
    prep_kernel<<<BB + PREP_CVT, 256>>>(mask, idx, nkeep, npad, kd32, rsum,
                                        x, Wq, Wk, Wv, xh, Wqh, Wkvh);

    // #1: merged Q + K|V projections (KV gathers A rows through idx)
    {
        dim3 g(2 * DD / 128, SS / 128, 2 * BB);
        hgemm<7><<<g, 256, SMEMB>>>(xh, Wkvh, bk, bv, nullptr, Kc, Vtc,
                                    nullptr, nullptr,
                                    DD, DD, DD, DD, 1.0f, sBD, 0, sBD,
                                    npad, nullptr, nullptr, idx,
                                    xh, Wqh, bq, Qh);
    }

    // #2: scores -> unnormalized exp fp16 + row sums
    {
        dim3 g(SS / 128, SS / 128, BB);
        hgemm<5><<<g, 256, SMEMB>>>(Qh, Kc, nullptr, nullptr, nullptr, Ph, nullptr,
                                    rsum, nkeep,
                                    DD, DD, SS, DD, 1.0f / 32.0f,
                                    sBD, sBD, sSS,
                                    nullptr, npad, nullptr, nullptr,
                                    nullptr, nullptr, nullptr, nullptr);
    }

    // #3: out = (E @ Vtc^T) / rsum[row], dynamic K = kd32[b]
    {
        dim3 g(DD / 128, SS / 128, BB);
        hgemm<6><<<g, 256, SMEMB>>>(Ph, Vtc, nullptr, nullptr, out, nullptr, nullptr,
                                    rsum, nullptr,
                                    SS, SS, DD, DD, 1.0f,
                                    sSS, sBD, sBD,
                                    nullptr, nullptr, kd32, nullptr,
                                    nullptr, nullptr, nullptr, nullptr);
    }
}